// round 1
// baseline (speedup 1.0000x reference)
#include <cuda_runtime.h>
#include <cuda_bf16.h>
#include <math.h>

// Problem constants
#define S_ 2
#define B_ 2048
#define D_ 1024
#define H_ 2048
#define E_ 8
#define O_ 1024
#define T_ (S_*B_)        // 4096 tokens
#define P_ (T_*2)         // 8192 (token, k) pairs
#define MAXR 4096         // worst-case rows per expert
#define OUT_OFF ((size_t)B_*O_)

// Scratch (device globals — allocation-free per harness rules)
__device__ __align__(128) float g_H[(size_t)P_ * H_];     // 64 MB: relu(fc1) per pair
__device__ __align__(128) float g_Y[(size_t)P_ * H_];     // 64 MB: gate * (fc2 out) per pair
__device__ __align__(128) float g_comb[(size_t)B_ * H_];  // 16 MB: combined
__device__ __align__(128) float g_gate[P_];
__device__ __align__(128) int   g_list[E_ * MAXR];
__device__ int   g_cnt[E_];

// Packed dual fp32 FMA (Blackwell FFMA2) — only reachable via PTX
__device__ __forceinline__ void ffma2(float2 &d, float2 a, float2 b) {
    unsigned long long &dd = reinterpret_cast<unsigned long long &>(d);
    unsigned long long &aa = reinterpret_cast<unsigned long long &>(a);
    unsigned long long &bb = reinterpret_cast<unsigned long long &>(b);
    asm("fma.rn.f32x2 %0, %1, %2, %0;" : "+l"(dd) : "l"(aa), "l"(bb));
}

__global__ void zero_kernel() {
    if (threadIdx.x < E_) g_cnt[threadIdx.x] = 0;
}

// Gating: Hg = xs @ Wg + b; expert_probs = softmax(Hg); top-2 gates; routing lists.
__global__ __launch_bounds__(256) void gating_kernel(
        const float* __restrict__ xs, const float* __restrict__ Wg,
        const float* __restrict__ bias, float* __restrict__ out)
{
    __shared__ __align__(16) float ws[E_][D_];   // Wg transposed, 32 KB
    int tid = threadIdx.x;
    for (int i = tid; i < E_*D_; i += 256) {
        int e = i >> 10, d = i & (D_-1);
        ws[e][d] = Wg[d*E_ + e];
    }
    __syncthreads();
    int warp = tid >> 5, lane = tid & 31;
    for (int tt = 0; tt < 8; ++tt) {
        int t = blockIdx.x * 64 + warp * 8 + tt;   // 64 blocks x 64 tokens
        float acc[E_];
        #pragma unroll
        for (int e = 0; e < E_; ++e) acc[e] = 0.f;
        const float4* xrow = reinterpret_cast<const float4*>(xs + (size_t)t * D_);
        #pragma unroll
        for (int it = 0; it < D_/128; ++it) {
            float4 x = xrow[lane + it*32];
            #pragma unroll
            for (int e = 0; e < E_; ++e) {
                float4 w = reinterpret_cast<const float4*>(ws[e])[lane + it*32];
                acc[e] += x.x*w.x + x.y*w.y + x.z*w.z + x.w*w.w;
            }
        }
        #pragma unroll
        for (int off = 16; off > 0; off >>= 1) {
            #pragma unroll
            for (int e = 0; e < E_; ++e)
                acc[e] += __shfl_xor_sync(0xffffffffu, acc[e], off);
        }
        if (lane == 0) {
            float h[E_];
            #pragma unroll
            for (int e = 0; e < E_; ++e) h[e] = acc[e] + bias[e];
            float m1 = h[0]; int i1 = 0;
            #pragma unroll
            for (int e = 1; e < E_; ++e) if (h[e] > m1) { m1 = h[e]; i1 = e; }
            float m2 = -3.0e38f; int i2 = 0;
            #pragma unroll
            for (int e = 0; e < E_; ++e) if (e != i1 && h[e] > m2) { m2 = h[e]; i2 = e; }
            // full softmax -> expert_probs output
            float pr[E_]; float den = 0.f;
            #pragma unroll
            for (int e = 0; e < E_; ++e) { pr[e] = expf(h[e] - m1); den += pr[e]; }
            float inv = 1.f / den;
            float* ep = out + OUT_OFF + (size_t)t * E_;
            #pragma unroll
            for (int e = 0; e < E_; ++e) ep[e] = pr[e] * inv;
            // top-2 renormalized gates (softmax over masked == 2-way softmax)
            float l2 = expf(m2 - m1);
            float gd = 1.f + l2;
            g_gate[t*2]     = 1.f / gd;
            g_gate[t*2 + 1] = l2 / gd;
            int pos = atomicAdd(&g_cnt[i1], 1); g_list[i1*MAXR + pos] = t*2;
            pos     = atomicAdd(&g_cnt[i2], 1); g_list[i2*MAXR + pos] = t*2 + 1;
        }
    }
}

// ---------- tiled fp32 GEMM with f32x2 packed FMA ----------
#define BM 128
#define BN 128
#define BK 16
#define KH (BK/2)

// MODE 1: A = xs rows gathered by token (p>>1); epilogue relu(+fc1_b)  -> g_H[p]
// MODE 2: A = g_H rows gathered by p;         epilogue (+fc2_b)*gate   -> g_Y[p]
template<int MODE>
__global__ __launch_bounds__(256, 1) void moe_gemm(
        const float* __restrict__ Axs, const float* __restrict__ W,
        const float* __restrict__ bias, int K)
{
    int e = blockIdx.z;
    int cnt = g_cnt[e];
    int row0 = blockIdx.y * BM;
    if (row0 >= cnt) return;
    const int* lst = g_list + e * MAXR;
    const float* Wb = W + (size_t)e * H_ * K;
    const float* bb = bias + (size_t)e * H_;
    const float* Abase = (MODE == 1) ? Axs : g_H;
    float* Cbase = (MODE == 1) ? g_H : g_Y;
    int n0blk = blockIdx.x * BN;

    __shared__ __align__(16) float2 As2[KH][BM];  // k-pair interleaved
    __shared__ __align__(16) float2 Bs2[KH][BN];

    int tid = threadIdx.x;
    int tx = tid & 15, ty = tid >> 4;
    int m0 = ty * 8, n0 = tx * 8;

    int rA = tid >> 2;           // 0..63 (+64 for second half)
    int kq = (tid & 3) * 4;      // 0,4,8,12
    int k2s = kq >> 1;
    const float* arow[2]; bool aval[2];
    const float* brow[2];
    #pragma unroll
    for (int l = 0; l < 2; ++l) {
        int gr = row0 + rA + l*64;
        aval[l] = gr < cnt;
        int p = aval[l] ? lst[gr] : 0;
        int ridx = (MODE == 1) ? (p >> 1) : p;
        arow[l] = Abase + (size_t)ridx * K + kq;
        brow[l] = Wb + (size_t)(n0blk + rA + l*64) * K + kq;
    }

    float2 acc[8][8];
    #pragma unroll
    for (int i = 0; i < 8; ++i)
        #pragma unroll
        for (int j = 0; j < 8; ++j) acc[i][j] = make_float2(0.f, 0.f);

    for (int k0 = 0; k0 < K; k0 += BK) {
        #pragma unroll
        for (int l = 0; l < 2; ++l) {
            int r = rA + l*64;
            float4 v = aval[l] ? *reinterpret_cast<const float4*>(arow[l] + k0)
                               : make_float4(0.f, 0.f, 0.f, 0.f);
            As2[k2s][r]     = make_float2(v.x, v.y);
            As2[k2s + 1][r] = make_float2(v.z, v.w);
            float4 w = *reinterpret_cast<const float4*>(brow[l] + k0);
            Bs2[k2s][r]     = make_float2(w.x, w.y);
            Bs2[k2s + 1][r] = make_float2(w.z, w.w);
        }
        __syncthreads();
        #pragma unroll
        for (int k2 = 0; k2 < KH; ++k2) {
            float2 a[8], b[8];
            const float4* av = reinterpret_cast<const float4*>(&As2[k2][m0]);
            const float4* bv = reinterpret_cast<const float4*>(&Bs2[k2][n0]);
            #pragma unroll
            for (int q = 0; q < 4; ++q) {
                float4 t = av[q];
                a[q*2]   = make_float2(t.x, t.y);
                a[q*2+1] = make_float2(t.z, t.w);
                float4 u = bv[q];
                b[q*2]   = make_float2(u.x, u.y);
                b[q*2+1] = make_float2(u.z, u.w);
            }
            #pragma unroll
            for (int i = 0; i < 8; ++i)
                #pragma unroll
                for (int j = 0; j < 8; ++j)
                    ffma2(acc[i][j], a[i], b[j]);
        }
        __syncthreads();
    }

    #pragma unroll
    for (int i = 0; i < 8; ++i) {
        int gr = row0 + m0 + i;
        if (gr >= cnt) continue;
        int p = lst[gr];
        float gate = (MODE == 2) ? g_gate[p] : 1.f;
        float* crow = Cbase + (size_t)p * H_ + n0blk + n0;
        #pragma unroll
        for (int jq = 0; jq < 2; ++jq) {
            float r[4];
            #pragma unroll
            for (int q = 0; q < 4; ++q) {
                int j = jq*4 + q;
                float v = acc[i][j].x + acc[i][j].y + bb[n0blk + n0 + j];
                if (MODE == 1) v = fmaxf(v, 0.f);
                else           v *= gate;
                r[q] = v;
            }
            *reinterpret_cast<float4*>(crow + jq*4) = make_float4(r[0], r[1], r[2], r[3]);
        }
    }
}

// combined[b][g] = 0.5 * sum of the 4 pair contributions for this b (deterministic order)
__global__ void combine_kernel() {
    int idx = blockIdx.x * blockDim.x + threadIdx.x;  // over 2048 x 512 float4
    int b  = idx >> 9;
    int gq = idx & 511;
    const float4* Y = reinterpret_cast<const float4*>(g_Y);
    size_t base0 = ((size_t)(b)        * 2) * (H_/4) + gq;   // s=0 token
    size_t base1 = ((size_t)(B_ + b)   * 2) * (H_/4) + gq;   // s=1 token
    float4 y0 = Y[base0], y1 = Y[base0 + H_/4];
    float4 y2 = Y[base1], y3 = Y[base1 + H_/4];
    float4 o;
    o.x = 0.5f * (y0.x + y1.x + y2.x + y3.x);
    o.y = 0.5f * (y0.y + y1.y + y2.y + y3.y);
    o.z = 0.5f * (y0.z + y1.z + y2.z + y3.z);
    o.w = 0.5f * (y0.w + y1.w + y2.w + y3.w);
    reinterpret_cast<float4*>(g_comb)[(size_t)b * (H_/4) + gq] = o;
}

// out[b][o] = combined[b] . final_w[o] + final_b[o]   (M=2048, N=1024, K=2048)
__global__ __launch_bounds__(256, 1) void final_gemm(
        const float* __restrict__ W, const float* __restrict__ bias,
        float* __restrict__ out)
{
    const int K = H_;
    int row0 = blockIdx.y * BM;
    int n0blk = blockIdx.x * BN;

    __shared__ __align__(16) float2 As2[KH][BM];
    __shared__ __align__(16) float2 Bs2[KH][BN];

    int tid = threadIdx.x;
    int tx = tid & 15, ty = tid >> 4;
    int m0 = ty * 8, n0 = tx * 8;

    int rA = tid >> 2;
    int kq = (tid & 3) * 4;
    int k2s = kq >> 1;
    const float* arow[2];
    const float* brow[2];
    #pragma unroll
    for (int l = 0; l < 2; ++l) {
        arow[l] = g_comb + (size_t)(row0 + rA + l*64) * K + kq;
        brow[l] = W + (size_t)(n0blk + rA + l*64) * K + kq;
    }

    float2 acc[8][8];
    #pragma unroll
    for (int i = 0; i < 8; ++i)
        #pragma unroll
        for (int j = 0; j < 8; ++j) acc[i][j] = make_float2(0.f, 0.f);

    for (int k0 = 0; k0 < K; k0 += BK) {
        #pragma unroll
        for (int l = 0; l < 2; ++l) {
            int r = rA + l*64;
            float4 v = *reinterpret_cast<const float4*>(arow[l] + k0);
            As2[k2s][r]     = make_float2(v.x, v.y);
            As2[k2s + 1][r] = make_float2(v.z, v.w);
            float4 w = *reinterpret_cast<const float4*>(brow[l] + k0);
            Bs2[k2s][r]     = make_float2(w.x, w.y);
            Bs2[k2s + 1][r] = make_float2(w.z, w.w);
        }
        __syncthreads();
        #pragma unroll
        for (int k2 = 0; k2 < KH; ++k2) {
            float2 a[8], b[8];
            const float4* av = reinterpret_cast<const float4*>(&As2[k2][m0]);
            const float4* bv = reinterpret_cast<const float4*>(&Bs2[k2][n0]);
            #pragma unroll
            for (int q = 0; q < 4; ++q) {
                float4 t = av[q];
                a[q*2]   = make_float2(t.x, t.y);
                a[q*2+1] = make_float2(t.z, t.w);
                float4 u = bv[q];
                b[q*2]   = make_float2(u.x, u.y);
                b[q*2+1] = make_float2(u.z, u.w);
            }
            #pragma unroll
            for (int i = 0; i < 8; ++i)
                #pragma unroll
                for (int j = 0; j < 8; ++j)
                    ffma2(acc[i][j], a[i], b[j]);
        }
        __syncthreads();
    }

    #pragma unroll
    for (int i = 0; i < 8; ++i) {
        float* crow = out + (size_t)(row0 + m0 + i) * O_ + n0blk + n0;
        #pragma unroll
        for (int jq = 0; jq < 2; ++jq) {
            float r[4];
            #pragma unroll
            for (int q = 0; q < 4; ++q) {
                int j = jq*4 + q;
                r[q] = acc[i][j].x + acc[i][j].y + bias[n0blk + n0 + j];
            }
            *reinterpret_cast<float4*>(crow + jq*4) = make_float4(r[0], r[1], r[2], r[3]);
        }
    }
}

extern "C" void kernel_launch(void* const* d_in, const int* in_sizes, int n_in,
                              void* d_out, int out_size) {
    const float* xs      = (const float*)d_in[0];
    const float* Wg      = (const float*)d_in[1];
    const float* b       = (const float*)d_in[2];
    const float* fc1_w   = (const float*)d_in[3];
    const float* fc1_b   = (const float*)d_in[4];
    const float* fc2_w   = (const float*)d_in[5];
    const float* fc2_b   = (const float*)d_in[6];
    const float* final_w = (const float*)d_in[7];
    const float* final_b = (const float*)d_in[8];
    float* out = (float*)d_out;

    zero_kernel<<<1, 32>>>();
    gating_kernel<<<T_/64, 256>>>(xs, Wg, b, out);
    dim3 g1(H_/BN, MAXR/BM, E_);
    moe_gemm<1><<<g1, 256>>>(xs, fc1_w, fc1_b, D_);
    moe_gemm<2><<<g1, 256>>>(nullptr, fc2_w, fc2_b, H_);
    combine_kernel<<<(B_*(H_/4))/256, 256>>>();
    dim3 gf(O_/BN, B_/BM);
    final_gemm<<<gf, 256>>>(final_w, final_b, out);
}

// round 3
// speedup vs baseline: 3.5249x; 3.5249x over previous
#include <cuda_runtime.h>
#include <cuda_bf16.h>
#include <math.h>
#include <stdint.h>

// Problem constants
#define S_ 2
#define B_ 2048
#define D_ 1024
#define H_ 2048
#define E_ 8
#define O_ 1024
#define T_ (S_*B_)        // 4096 tokens
#define P_ (T_*2)         // 8192 (token, k) pairs
#define MAXR 4096
#define OUT_OFF ((size_t)B_*O_)

// Scratch
__device__ __align__(128) float g_H[(size_t)P_ * H_];
__device__ __align__(128) float g_Y[(size_t)P_ * H_];
__device__ __align__(128) float g_comb[(size_t)B_ * H_];
__device__ __align__(128) float g_gate[P_];
__device__ __align__(128) int   g_list[E_ * MAXR];
__device__ int   g_cnt[E_];

__device__ __forceinline__ uint32_t smem_u32(const void* p) {
    uint32_t a;
    asm("{ .reg .u64 t; cvta.to.shared.u64 t, %1; cvt.u32.u64 %0, t; }" : "=r"(a) : "l"(p));
    return a;
}

#define LDSM4(r0, r1, r2, r3, addr) \
    asm volatile("ldmatrix.sync.aligned.m8n8.x4.shared.b16 {%0,%1,%2,%3}, [%4];" \
        : "=r"(r0), "=r"(r1), "=r"(r2), "=r"(r3) : "r"(addr))

#define MMA16816(d, a, b) \
    asm volatile("mma.sync.aligned.m16n8k16.row.col.f32.bf16.bf16.f32 " \
        "{%0,%1,%2,%3}, {%4,%5,%6,%7}, {%8,%9}, {%0,%1,%2,%3};" \
        : "+f"((d)[0]), "+f"((d)[1]), "+f"((d)[2]), "+f"((d)[3]) \
        : "r"((a)[0]), "r"((a)[1]), "r"((a)[2]), "r"((a)[3]), \
          "r"((b)[0]), "r"((b)[1]))

// hi/lo bf16 split of 2 packed floats
__device__ __forceinline__ void split2(float a, float b, uint32_t &hi, uint32_t &lo) {
    __nv_bfloat162 h = __floats2bfloat162_rn(a, b);
    float la = a - __low2float(h);
    float lb = b - __high2float(h);
    __nv_bfloat162 l = __floats2bfloat162_rn(la, lb);
    hi = *reinterpret_cast<uint32_t*>(&h);
    lo = *reinterpret_cast<uint32_t*>(&l);
}

// swizzled offset within one 128-row x 16-k bf16 region (32B rows)
__device__ __forceinline__ int swoff(int r, int c) {
    return r * 32 + ((c ^ ((r >> 2) & 1)) << 4);
}

__global__ void zero_kernel() {
    if (threadIdx.x < E_) g_cnt[threadIdx.x] = 0;
}

// ------------------------- gating -------------------------
__global__ __launch_bounds__(256) void gating_kernel(
        const float* __restrict__ xs, const float* __restrict__ Wg,
        const float* __restrict__ bias, float* __restrict__ out)
{
    __shared__ __align__(16) float ws[E_][D_];
    int tid = threadIdx.x;
    for (int i = tid; i < E_*D_; i += 256) {
        int e = i >> 10, d = i & (D_-1);
        ws[e][d] = Wg[d*E_ + e];
    }
    __syncthreads();
    int warp = tid >> 5, lane = tid & 31;
    for (int tt = 0; tt < 8; ++tt) {
        int t = blockIdx.x * 64 + warp * 8 + tt;
        float acc[E_];
        #pragma unroll
        for (int e = 0; e < E_; ++e) acc[e] = 0.f;
        const float4* xrow = reinterpret_cast<const float4*>(xs + (size_t)t * D_);
        #pragma unroll
        for (int it = 0; it < D_/128; ++it) {
            float4 x = xrow[lane + it*32];
            #pragma unroll
            for (int e = 0; e < E_; ++e) {
                float4 w = reinterpret_cast<const float4*>(ws[e])[lane + it*32];
                acc[e] += x.x*w.x + x.y*w.y + x.z*w.z + x.w*w.w;
            }
        }
        #pragma unroll
        for (int off = 16; off > 0; off >>= 1) {
            #pragma unroll
            for (int e = 0; e < E_; ++e)
                acc[e] += __shfl_xor_sync(0xffffffffu, acc[e], off);
        }
        if (lane == 0) {
            float h[E_];
            #pragma unroll
            for (int e = 0; e < E_; ++e) h[e] = acc[e] + bias[e];
            float m1 = h[0]; int i1 = 0;
            #pragma unroll
            for (int e = 1; e < E_; ++e) if (h[e] > m1) { m1 = h[e]; i1 = e; }
            float m2 = -3.0e38f; int i2 = 0;
            #pragma unroll
            for (int e = 0; e < E_; ++e) if (e != i1 && h[e] > m2) { m2 = h[e]; i2 = e; }
            float pr[E_]; float den = 0.f;
            #pragma unroll
            for (int e = 0; e < E_; ++e) { pr[e] = expf(h[e] - m1); den += pr[e]; }
            float inv = 1.f / den;
            float* ep = out + OUT_OFF + (size_t)t * E_;
            #pragma unroll
            for (int e = 0; e < E_; ++e) ep[e] = pr[e] * inv;
            float l2 = expf(m2 - m1);
            float gd = 1.f + l2;
            g_gate[t*2]     = 1.f / gd;
            g_gate[t*2 + 1] = l2 / gd;
            int pos = atomicAdd(&g_cnt[i1], 1); g_list[i1*MAXR + pos] = t*2;
            pos     = atomicAdd(&g_cnt[i2], 1); g_list[i2*MAXR + pos] = t*2 + 1;
        }
    }
}

// --------------- mma.sync split-bf16 GEMM (128x128 tile, BK=16) ---------------
// MODE 0: final (A=g_comb, W=final_w, C=out, K=2048, N=1024)
// MODE 1: fc1   (A=xs by token, W=fc1_w[e], C=g_H, K=1024, N=2048, relu)
// MODE 2: fc2   (A=g_H by pair, W=fc2_w[e], C=g_Y, K=2048, N=2048, *gate)
template<int MODE>
__global__ __launch_bounds__(256, 1) void mma_gemm(
        const float* __restrict__ Ain, const float* __restrict__ Wfull,
        const float* __restrict__ biasF, float* __restrict__ Cout)
{
    constexpr int K    = (MODE == 1) ? 1024 : 2048;
    constexpr int NTOT = (MODE == 0) ? 1024 : 2048;
    constexpr int NC   = K / 16;

    int e = (MODE == 0) ? 0 : blockIdx.z;
    int cnt;
    const int* lst = nullptr;
    if (MODE == 0) cnt = B_;
    else { cnt = g_cnt[e]; lst = g_list + e * MAXR; }
    int row0 = blockIdx.y * 128;
    if (row0 >= cnt) return;
    int n0blk = blockIdx.x * 128;
    const float* Wb = Wfull + (size_t)e * NTOT * K;
    const float* bb = biasF + (size_t)e * ((MODE == 0) ? 0 : NTOT);

    // [stage][region: Ahi,Alo,Bhi,Blo][128 rows x 32B]
    __shared__ __align__(1024) unsigned char sm[2][4][4096];
    uint32_t su = smem_u32(sm);

    int tid = threadIdx.x;
    int wid = tid >> 5, lane = tid & 31;
    int warp_m = wid >> 2;        // 0..1, 64 rows each
    int warp_n = wid & 3;         // 0..3, 32 cols each

    // ---- staging-load assignment: row lr (0..127), k-chunk lc (0..1, 8 floats) ----
    int lr = tid >> 1, lc = tid & 1;
    const float* aP;
    {
        int gr = row0 + lr;
        int ridx;
        if (MODE == 0) ridx = gr;
        else {
            int p = (gr < cnt) ? lst[gr] : lst[0];
            ridx = (MODE == 1) ? (p >> 1) : p;
        }
        aP = Ain + (size_t)ridx * K + lc * 8;
    }
    const float* bP = Wb + (size_t)(n0blk + lr) * K + lc * 8;
    int offS = swoff(lr, lc);

    // ---- ldmatrix address offsets (per warp) ----
    int aoffs[4], boffs[2];
    {
        int ar = warp_m * 64 + (lane & 15);
        int ac = lane >> 4;
        #pragma unroll
        for (int t = 0; t < 4; ++t) aoffs[t] = swoff(ar + t * 16, ac);
        int br = warp_n * 32 + (lane & 7) + ((lane >> 4) << 3);
        int bc = (lane >> 3) & 1;
        #pragma unroll
        for (int jj = 0; jj < 2; ++jj) boffs[jj] = swoff(br + jj * 16, bc);
    }

    float acc[4][4][4];
    #pragma unroll
    for (int t = 0; t < 4; ++t)
        #pragma unroll
        for (int j = 0; j < 4; ++j)
            #pragma unroll
            for (int q = 0; q < 4; ++q) acc[t][j][q] = 0.f;

    float4 ra0, ra1, rb0, rb1;

    // prologue: stage 0
    ra0 = *reinterpret_cast<const float4*>(aP);
    ra1 = *reinterpret_cast<const float4*>(aP + 4);
    rb0 = *reinterpret_cast<const float4*>(bP);
    rb1 = *reinterpret_cast<const float4*>(bP + 4);
    {
        uint4 hi, lo;
        split2(ra0.x, ra0.y, hi.x, lo.x); split2(ra0.z, ra0.w, hi.y, lo.y);
        split2(ra1.x, ra1.y, hi.z, lo.z); split2(ra1.z, ra1.w, hi.w, lo.w);
        *reinterpret_cast<uint4*>(&sm[0][0][offS]) = hi;
        *reinterpret_cast<uint4*>(&sm[0][1][offS]) = lo;
        split2(rb0.x, rb0.y, hi.x, lo.x); split2(rb0.z, rb0.w, hi.y, lo.y);
        split2(rb1.x, rb1.y, hi.z, lo.z); split2(rb1.z, rb1.w, hi.w, lo.w);
        *reinterpret_cast<uint4*>(&sm[0][2][offS]) = hi;
        *reinterpret_cast<uint4*>(&sm[0][3][offS]) = lo;
    }
    __syncthreads();

    for (int c = 0; c < NC; ++c) {
        // prefetch next stage into registers
        if (c + 1 < NC) {
            const float* ap = aP + (c + 1) * 16;
            const float* bp = bP + (c + 1) * 16;
            ra0 = *reinterpret_cast<const float4*>(ap);
            ra1 = *reinterpret_cast<const float4*>(ap + 4);
            rb0 = *reinterpret_cast<const float4*>(bp);
            rb1 = *reinterpret_cast<const float4*>(bp + 4);
        }

        // compute on buffer c&1
        uint32_t base = su + (c & 1) * 16384;
        uint32_t Ah[4][4], Al[4][4], Bh[4][2], Bl[4][2];
        #pragma unroll
        for (int t = 0; t < 4; ++t) {
            LDSM4(Ah[t][0], Ah[t][1], Ah[t][2], Ah[t][3], base + aoffs[t]);
            LDSM4(Al[t][0], Al[t][1], Al[t][2], Al[t][3], base + 4096 + aoffs[t]);
        }
        #pragma unroll
        for (int jj = 0; jj < 2; ++jj) {
            LDSM4(Bh[2*jj][0], Bh[2*jj][1], Bh[2*jj+1][0], Bh[2*jj+1][1],
                  base + 8192 + boffs[jj]);
            LDSM4(Bl[2*jj][0], Bl[2*jj][1], Bl[2*jj+1][0], Bl[2*jj+1][1],
                  base + 12288 + boffs[jj]);
        }
        #pragma unroll
        for (int t = 0; t < 4; ++t)
            #pragma unroll
            for (int j = 0; j < 4; ++j)
                MMA16816(acc[t][j], Ah[t], Bh[j]);
        #pragma unroll
        for (int t = 0; t < 4; ++t)
            #pragma unroll
            for (int j = 0; j < 4; ++j)
                MMA16816(acc[t][j], Al[t], Bh[j]);
        #pragma unroll
        for (int t = 0; t < 4; ++t)
            #pragma unroll
            for (int j = 0; j < 4; ++j)
                MMA16816(acc[t][j], Ah[t], Bl[j]);

        // store next stage
        if (c + 1 < NC) {
            unsigned char* st = &sm[(c + 1) & 1][0][0];
            uint4 hi, lo;
            split2(ra0.x, ra0.y, hi.x, lo.x); split2(ra0.z, ra0.w, hi.y, lo.y);
            split2(ra1.x, ra1.y, hi.z, lo.z); split2(ra1.z, ra1.w, hi.w, lo.w);
            *reinterpret_cast<uint4*>(st + offS)        = hi;
            *reinterpret_cast<uint4*>(st + 4096 + offS) = lo;
            split2(rb0.x, rb0.y, hi.x, lo.x); split2(rb0.z, rb0.w, hi.y, lo.y);
            split2(rb1.x, rb1.y, hi.z, lo.z); split2(rb1.z, rb1.w, hi.w, lo.w);
            *reinterpret_cast<uint4*>(st + 8192 + offS)  = hi;
            *reinterpret_cast<uint4*>(st + 12288 + offS) = lo;
        }
        __syncthreads();
    }

    // ---- epilogue ----
    int mwarp = row0 + warp_m * 64;
    #pragma unroll
    for (int t = 0; t < 4; ++t) {
        #pragma unroll
        for (int half = 0; half < 2; ++half) {
            int gr = mwarp + t * 16 + (lane >> 2) + half * 8;
            bool valid = gr < cnt;
            float gate = 1.f;
            float* crow = nullptr;
            if (valid) {
                if (MODE == 0) crow = Cout + (size_t)gr * O_;
                else {
                    int p = lst[gr];
                    if (MODE == 1) crow = g_H + (size_t)p * H_;
                    else { crow = g_Y + (size_t)p * H_; gate = g_gate[p]; }
                }
            }
            if (!valid) continue;
            #pragma unroll
            for (int j = 0; j < 4; ++j) {
                int n = n0blk + warp_n * 32 + j * 8 + (lane & 3) * 2;
                float v0 = acc[t][j][half*2 + 0] + bb[n];
                float v1 = acc[t][j][half*2 + 1] + bb[n + 1];
                if (MODE == 1) { v0 = fmaxf(v0, 0.f); v1 = fmaxf(v1, 0.f); }
                else if (MODE == 2) { v0 *= gate; v1 *= gate; }
                *reinterpret_cast<float2*>(crow + n) = make_float2(v0, v1);
            }
        }
    }
}

// ------------------------- combine -------------------------
__global__ void combine_kernel() {
    int idx = blockIdx.x * blockDim.x + threadIdx.x;
    int b  = idx >> 9;
    int gq = idx & 511;
    const float4* Y = reinterpret_cast<const float4*>(g_Y);
    size_t base0 = ((size_t)(b)      * 2) * (H_/4) + gq;
    size_t base1 = ((size_t)(B_ + b) * 2) * (H_/4) + gq;
    float4 y0 = Y[base0], y1 = Y[base0 + H_/4];
    float4 y2 = Y[base1], y3 = Y[base1 + H_/4];
    float4 o;
    o.x = 0.5f * (y0.x + y1.x + y2.x + y3.x);
    o.y = 0.5f * (y0.y + y1.y + y2.y + y3.y);
    o.z = 0.5f * (y0.z + y1.z + y2.z + y3.z);
    o.w = 0.5f * (y0.w + y1.w + y2.w + y3.w);
    reinterpret_cast<float4*>(g_comb)[(size_t)b * (H_/4) + gq] = o;
}

extern "C" void kernel_launch(void* const* d_in, const int* in_sizes, int n_in,
                              void* d_out, int out_size) {
    const float* xs      = (const float*)d_in[0];
    const float* Wg      = (const float*)d_in[1];
    const float* b       = (const float*)d_in[2];
    const float* fc1_w   = (const float*)d_in[3];
    const float* fc1_b   = (const float*)d_in[4];
    const float* fc2_w   = (const float*)d_in[5];
    const float* fc2_b   = (const float*)d_in[6];
    const float* final_w = (const float*)d_in[7];
    const float* final_b = (const float*)d_in[8];
    float* out = (float*)d_out;

    float* comb_ptr = nullptr;
    cudaGetSymbolAddress((void**)&comb_ptr, g_comb);
    float* gH_ptr = nullptr;
    cudaGetSymbolAddress((void**)&gH_ptr, g_H);

    zero_kernel<<<1, 32>>>();
    gating_kernel<<<T_/64, 256>>>(xs, Wg, b, out);

    dim3 g1(H_/128, MAXR/128, E_);
    mma_gemm<1><<<g1, 256>>>(xs, fc1_w, fc1_b, nullptr);
    mma_gemm<2><<<g1, 256>>>(gH_ptr, fc2_w, fc2_b, nullptr);
    combine_kernel<<<(B_*(H_/4))/256, 256>>>();
    dim3 gf(O_/128, B_/128);
    mma_gemm<0><<<gf, 256>>>(comb_ptr, final_w, final_b, out);
}

// round 4
// speedup vs baseline: 3.9718x; 1.1268x over previous
#include <cuda_runtime.h>
#include <cuda_bf16.h>
#include <math.h>
#include <stdint.h>

// Problem constants
#define S_ 2
#define B_ 2048
#define D_ 1024
#define H_ 2048
#define E_ 8
#define O_ 1024
#define T_ (S_*B_)        // 4096 tokens
#define P_ (T_*2)         // 8192 (token, k) pairs
#define MAXR 4096
#define OUT_OFF ((size_t)B_*O_)

// ---------------- scratch (device globals) ----------------
__device__ __align__(128) __nv_bfloat16 g_xh[(size_t)T_ * D_];
__device__ __align__(128) __nv_bfloat16 g_xl[(size_t)T_ * D_];
__device__ __align__(128) __nv_bfloat16 g_w1h[(size_t)E_ * H_ * D_];
__device__ __align__(128) __nv_bfloat16 g_w1l[(size_t)E_ * H_ * D_];
__device__ __align__(128) __nv_bfloat16 g_w2h[(size_t)E_ * H_ * H_];
__device__ __align__(128) __nv_bfloat16 g_w2l[(size_t)E_ * H_ * H_];
__device__ __align__(128) __nv_bfloat16 g_fwh[(size_t)O_ * H_];
__device__ __align__(128) __nv_bfloat16 g_fwl[(size_t)O_ * H_];
__device__ __align__(128) __nv_bfloat16 g_Hh[(size_t)P_ * H_];
__device__ __align__(128) __nv_bfloat16 g_Hl[(size_t)P_ * H_];
__device__ __align__(128) float         g_Y[(size_t)P_ * H_];
__device__ __align__(128) __nv_bfloat16 g_ch[(size_t)B_ * H_];
__device__ __align__(128) __nv_bfloat16 g_cl[(size_t)B_ * H_];
__device__ __align__(128) float g_gate[P_];
__device__ __align__(128) int   g_list[E_ * MAXR];
__device__ int   g_cnt[E_];

__device__ __forceinline__ uint32_t smem_u32(const void* p) {
    uint32_t a;
    asm("{ .reg .u64 t; cvta.to.shared.u64 t, %1; cvt.u32.u64 %0, t; }" : "=r"(a) : "l"(p));
    return a;
}

#define LDSM4(r0, r1, r2, r3, addr) \
    asm volatile("ldmatrix.sync.aligned.m8n8.x4.shared.b16 {%0,%1,%2,%3}, [%4];" \
        : "=r"(r0), "=r"(r1), "=r"(r2), "=r"(r3) : "r"(addr))

#define MMA16816(d, a, b) \
    asm volatile("mma.sync.aligned.m16n8k16.row.col.f32.bf16.bf16.f32 " \
        "{%0,%1,%2,%3}, {%4,%5,%6,%7}, {%8,%9}, {%0,%1,%2,%3};" \
        : "+f"((d)[0]), "+f"((d)[1]), "+f"((d)[2]), "+f"((d)[3]) \
        : "r"((a)[0]), "r"((a)[1]), "r"((a)[2]), "r"((a)[3]), \
          "r"((b)[0]), "r"((b)[1]))

#define CPA16(dst, src, sz) \
    asm volatile("cp.async.cg.shared.global [%0], [%1], 16, %2;" \
        :: "r"(dst), "l"(src), "r"(sz) : "memory")
#define CPCOMMIT() asm volatile("cp.async.commit_group;" ::: "memory")
#define CPWAIT(n)  asm volatile("cp.async.wait_group %0;" :: "n"(n) : "memory")

// hi/lo bf16 split of 2 packed floats
__device__ __forceinline__ void split2(float a, float b, uint32_t &hi, uint32_t &lo) {
    __nv_bfloat162 h = __floats2bfloat162_rn(a, b);
    float la = a - __low2float(h);
    float lb = b - __high2float(h);
    __nv_bfloat162 l = __floats2bfloat162_rn(la, lb);
    hi = *reinterpret_cast<uint32_t*>(&h);
    lo = *reinterpret_cast<uint32_t*>(&l);
}

// swizzled byte offset within a 128-row x 32-col bf16 plane (64B rows)
__device__ __forceinline__ int swoff(int r, int c) {
    return r * 64 + ((c ^ ((r >> 1) & 3)) << 4);
}

__global__ void zero_kernel() {
    if (threadIdx.x < E_) g_cnt[threadIdx.x] = 0;
}

// ---------------- pack fp32 -> bf16 hi/lo planes ----------------
__global__ void pack_split(const float* __restrict__ src,
                           __nv_bfloat16* __restrict__ hi,
                           __nv_bfloat16* __restrict__ lo, int n4) {
    int i = blockIdx.x * blockDim.x + threadIdx.x;
    if (i >= n4) return;
    float4 v = reinterpret_cast<const float4*>(src)[i];
    uint2 h, l;
    split2(v.x, v.y, h.x, l.x);
    split2(v.z, v.w, h.y, l.y);
    reinterpret_cast<uint2*>(hi)[i] = h;
    reinterpret_cast<uint2*>(lo)[i] = l;
}

// ---------------- gating ----------------
__global__ __launch_bounds__(256) void gating_kernel(
        const float* __restrict__ xs, const float* __restrict__ Wg,
        const float* __restrict__ bias, float* __restrict__ out)
{
    __shared__ __align__(16) float ws[E_][D_];
    int tid = threadIdx.x;
    for (int i = tid; i < E_*D_; i += 256) {
        int e = i >> 10, d = i & (D_-1);
        ws[e][d] = Wg[d*E_ + e];
    }
    __syncthreads();
    int warp = tid >> 5, lane = tid & 31;
    for (int tt = 0; tt < 8; ++tt) {
        int t = blockIdx.x * 64 + warp * 8 + tt;
        float acc[E_];
        #pragma unroll
        for (int e = 0; e < E_; ++e) acc[e] = 0.f;
        const float4* xrow = reinterpret_cast<const float4*>(xs + (size_t)t * D_);
        #pragma unroll
        for (int it = 0; it < D_/128; ++it) {
            float4 x = xrow[lane + it*32];
            #pragma unroll
            for (int e = 0; e < E_; ++e) {
                float4 w = reinterpret_cast<const float4*>(ws[e])[lane + it*32];
                acc[e] += x.x*w.x + x.y*w.y + x.z*w.z + x.w*w.w;
            }
        }
        #pragma unroll
        for (int off = 16; off > 0; off >>= 1) {
            #pragma unroll
            for (int e = 0; e < E_; ++e)
                acc[e] += __shfl_xor_sync(0xffffffffu, acc[e], off);
        }
        if (lane == 0) {
            float h[E_];
            #pragma unroll
            for (int e = 0; e < E_; ++e) h[e] = acc[e] + bias[e];
            float m1 = h[0]; int i1 = 0;
            #pragma unroll
            for (int e = 1; e < E_; ++e) if (h[e] > m1) { m1 = h[e]; i1 = e; }
            float m2 = -3.0e38f; int i2 = 0;
            #pragma unroll
            for (int e = 0; e < E_; ++e) if (e != i1 && h[e] > m2) { m2 = h[e]; i2 = e; }
            float pr[E_]; float den = 0.f;
            #pragma unroll
            for (int e = 0; e < E_; ++e) { pr[e] = expf(h[e] - m1); den += pr[e]; }
            float inv = 1.f / den;
            float* ep = out + OUT_OFF + (size_t)t * E_;
            #pragma unroll
            for (int e = 0; e < E_; ++e) ep[e] = pr[e] * inv;
            float l2 = expf(m2 - m1);
            float gd = 1.f + l2;
            g_gate[t*2]     = 1.f / gd;
            g_gate[t*2 + 1] = l2 / gd;
            int pos = atomicAdd(&g_cnt[i1], 1); g_list[i1*MAXR + pos] = t*2;
            pos     = atomicAdd(&g_cnt[i2], 1); g_list[i2*MAXR + pos] = t*2 + 1;
        }
    }
}

// ---------- mma.sync split-bf16 GEMM: 128x128 tile, BK=32, 4-stage cp.async ----------
// MODE 0: final (A=g_ch/g_cl, W=g_fwh/l, C=out,   K=2048, N=1024)
// MODE 1: fc1   (A=g_xh/g_xl by token, W=g_w1h/l, C=g_Hh/g_Hl bf16 split, K=1024, N=2048, relu)
// MODE 2: fc2   (A=g_Hh/g_Hl by pair,  W=g_w2h/l, C=g_Y fp32, K=2048, N=2048, *gate)
#define STG_BYTES 32768       // 4 planes x 8KB
#define PL_A_HI 0
#define PL_A_LO 8192
#define PL_B_HI 16384
#define PL_B_LO 24576
#define GEMM_SMEM (4 * STG_BYTES)

template<int MODE>
__global__ __launch_bounds__(256, 1) void mma_gemm(
        const float* __restrict__ biasF, float* __restrict__ Cout)
{
    constexpr int K    = (MODE == 1) ? 1024 : 2048;
    constexpr int NTOT = (MODE == 0) ? 1024 : 2048;
    constexpr int NC   = K / 32;

    const __nv_bfloat16 *Ah_g, *Al_g, *Wh_g, *Wl_g;
    if (MODE == 0) { Ah_g = g_ch; Al_g = g_cl; Wh_g = g_fwh; Wl_g = g_fwl; }
    else if (MODE == 1) { Ah_g = g_xh; Al_g = g_xl; Wh_g = g_w1h; Wl_g = g_w1l; }
    else { Ah_g = g_Hh; Al_g = g_Hl; Wh_g = g_w2h; Wl_g = g_w2l; }

    int e = (MODE == 0) ? 0 : blockIdx.z;
    int cnt;
    const int* lst = nullptr;
    if (MODE == 0) cnt = B_;
    else { cnt = g_cnt[e]; lst = g_list + e * MAXR; }
    int row0 = blockIdx.y * 128;
    if (row0 >= cnt) return;
    int n0blk = blockIdx.x * 128;
    const __nv_bfloat16* Wbh = Wh_g + (size_t)e * NTOT * K;
    const __nv_bfloat16* Wbl = Wl_g + (size_t)e * NTOT * K;
    const float* bb = biasF + (size_t)e * ((MODE == 0) ? 0 : NTOT);

    extern __shared__ unsigned char sm[];
    uint32_t su = smem_u32(sm);

    int tid = threadIdx.x;
    int wid = tid >> 5, lane = tid & 31;
    int warp_m = wid >> 2;        // 0..1 (64 rows)
    int warp_n = wid & 3;         // 0..3 (32 cols)

    // ---- cp.async assignment: row lr = tid>>1, chunk pair cp = tid&1 ----
    int lr = tid >> 1, cpair = tid & 1;
    int gr_ld = row0 + lr;
    uint32_t aSz = (MODE == 0 || gr_ld < cnt) ? 16u : 0u;
    int aridx;
    if (MODE == 0) aridx = (gr_ld < cnt) ? gr_ld : 0;
    else {
        int p = (gr_ld < cnt) ? lst[gr_ld] : 0;
        aridx = (MODE == 1) ? (p >> 1) : p;
    }
    const __nv_bfloat16* aPh = Ah_g + (size_t)aridx * K + cpair * 16;
    const __nv_bfloat16* aPl = Al_g + (size_t)aridx * K + cpair * 16;
    const __nv_bfloat16* bPh = Wbh + (size_t)(n0blk + lr) * K + cpair * 16;
    const __nv_bfloat16* bPl = Wbl + (size_t)(n0blk + lr) * K + cpair * 16;
    int s0 = swoff(lr, cpair * 2);
    int s1 = swoff(lr, cpair * 2 + 1);

    // ---- ldmatrix offsets ----
    int aoffs[4][2], boffs[2][2];
    {
        int ar = warp_m * 64 + (lane & 15);
        int achi = lane >> 4;
        #pragma unroll
        for (int t = 0; t < 4; ++t)
            #pragma unroll
            for (int ks = 0; ks < 2; ++ks)
                aoffs[t][ks] = swoff(ar + t * 16, ks * 2 + achi);
        int br = warp_n * 32 + (lane & 7) + ((lane >> 4) << 3);
        int bchi = (lane >> 3) & 1;
        #pragma unroll
        for (int jj = 0; jj < 2; ++jj)
            #pragma unroll
            for (int ks = 0; ks < 2; ++ks)
                boffs[jj][ks] = swoff(br + jj * 16, ks * 2 + bchi);
    }

    float acc[4][4][4];
    #pragma unroll
    for (int t = 0; t < 4; ++t)
        #pragma unroll
        for (int j = 0; j < 4; ++j)
            #pragma unroll
            for (int q = 0; q < 4; ++q) acc[t][j][q] = 0.f;

    // stage issue
    auto issue = [&](int c) {
        uint32_t sb = su + (c & 3) * STG_BYTES;
        int k0 = c * 32;
        CPA16(sb + PL_A_HI + s0, aPh + k0,     aSz);
        CPA16(sb + PL_A_HI + s1, aPh + k0 + 8, aSz);
        CPA16(sb + PL_A_LO + s0, aPl + k0,     aSz);
        CPA16(sb + PL_A_LO + s1, aPl + k0 + 8, aSz);
        CPA16(sb + PL_B_HI + s0, bPh + k0,     16u);
        CPA16(sb + PL_B_HI + s1, bPh + k0 + 8, 16u);
        CPA16(sb + PL_B_LO + s0, bPl + k0,     16u);
        CPA16(sb + PL_B_LO + s1, bPl + k0 + 8, 16u);
    };

    issue(0); CPCOMMIT();
    issue(1); CPCOMMIT();
    issue(2); CPCOMMIT();

    for (int c = 0; c < NC; ++c) {
        CPWAIT(2);
        __syncthreads();
        if (c + 3 < NC) { issue(c + 3); CPCOMMIT(); }
        uint32_t base = su + (c & 3) * STG_BYTES;
        #pragma unroll
        for (int ks = 0; ks < 2; ++ks) {
            uint32_t Ah[4][4], Al[4][4], Bh[4][2], Bl[4][2];
            #pragma unroll
            for (int t = 0; t < 4; ++t) {
                LDSM4(Ah[t][0], Ah[t][1], Ah[t][2], Ah[t][3], base + PL_A_HI + aoffs[t][ks]);
                LDSM4(Al[t][0], Al[t][1], Al[t][2], Al[t][3], base + PL_A_LO + aoffs[t][ks]);
            }
            #pragma unroll
            for (int jj = 0; jj < 2; ++jj) {
                LDSM4(Bh[2*jj][0], Bh[2*jj][1], Bh[2*jj+1][0], Bh[2*jj+1][1],
                      base + PL_B_HI + boffs[jj][ks]);
                LDSM4(Bl[2*jj][0], Bl[2*jj][1], Bl[2*jj+1][0], Bl[2*jj+1][1],
                      base + PL_B_LO + boffs[jj][ks]);
            }
            #pragma unroll
            for (int t = 0; t < 4; ++t)
                #pragma unroll
                for (int j = 0; j < 4; ++j)
                    MMA16816(acc[t][j], Ah[t], Bh[j]);
            #pragma unroll
            for (int t = 0; t < 4; ++t)
                #pragma unroll
                for (int j = 0; j < 4; ++j)
                    MMA16816(acc[t][j], Al[t], Bh[j]);
            #pragma unroll
            for (int t = 0; t < 4; ++t)
                #pragma unroll
                for (int j = 0; j < 4; ++j)
                    MMA16816(acc[t][j], Ah[t], Bl[j]);
        }
    }

    // ---- epilogue ----
    int mwarp = row0 + warp_m * 64;
    #pragma unroll
    for (int t = 0; t < 4; ++t) {
        #pragma unroll
        for (int half = 0; half < 2; ++half) {
            int gr = mwarp + t * 16 + (lane >> 2) + half * 8;
            if (gr >= cnt) continue;
            float gate = 1.f;
            float* crowf = nullptr;
            __nv_bfloat16 *crh = nullptr, *crl = nullptr;
            if (MODE == 0) crowf = Cout + (size_t)gr * O_;
            else {
                int p = lst[gr];
                if (MODE == 1) {
                    crh = g_Hh + (size_t)p * H_;
                    crl = g_Hl + (size_t)p * H_;
                } else {
                    crowf = g_Y + (size_t)p * H_;
                    gate = g_gate[p];
                }
            }
            #pragma unroll
            for (int j = 0; j < 4; ++j) {
                int n = n0blk + warp_n * 32 + j * 8 + (lane & 3) * 2;
                float v0 = acc[t][j][half*2 + 0] + bb[n];
                float v1 = acc[t][j][half*2 + 1] + bb[n + 1];
                if (MODE == 1) {
                    v0 = fmaxf(v0, 0.f); v1 = fmaxf(v1, 0.f);
                    uint32_t h, l;
                    split2(v0, v1, h, l);
                    *reinterpret_cast<uint32_t*>(crh + n) = h;
                    *reinterpret_cast<uint32_t*>(crl + n) = l;
                } else {
                    if (MODE == 2) { v0 *= gate; v1 *= gate; }
                    *reinterpret_cast<float2*>(crowf + n) = make_float2(v0, v1);
                }
            }
        }
    }
}

// ---------------- combine: sum 4 pair rows, /S, split to bf16 planes ----------------
__global__ void combine_kernel() {
    int idx = blockIdx.x * blockDim.x + threadIdx.x;
    int b  = idx >> 9;
    int gq = idx & 511;
    const float4* Y = reinterpret_cast<const float4*>(g_Y);
    size_t base0 = ((size_t)(b)      * 2) * (H_/4) + gq;
    size_t base1 = ((size_t)(B_ + b) * 2) * (H_/4) + gq;
    float4 y0 = Y[base0], y1 = Y[base0 + H_/4];
    float4 y2 = Y[base1], y3 = Y[base1 + H_/4];
    float4 o;
    o.x = 0.5f * (y0.x + y1.x + y2.x + y3.x);
    o.y = 0.5f * (y0.y + y1.y + y2.y + y3.y);
    o.z = 0.5f * (y0.z + y1.z + y2.z + y3.z);
    o.w = 0.5f * (y0.w + y1.w + y2.w + y3.w);
    uint2 h, l;
    split2(o.x, o.y, h.x, l.x);
    split2(o.z, o.w, h.y, l.y);
    size_t off = (size_t)b * (H_/4) + gq;
    reinterpret_cast<uint2*>(g_ch)[off] = h;
    reinterpret_cast<uint2*>(g_cl)[off] = l;
}

extern "C" void kernel_launch(void* const* d_in, const int* in_sizes, int n_in,
                              void* d_out, int out_size) {
    const float* xs      = (const float*)d_in[0];
    const float* Wg      = (const float*)d_in[1];
    const float* b       = (const float*)d_in[2];
    const float* fc1_w   = (const float*)d_in[3];
    const float* fc1_b   = (const float*)d_in[4];
    const float* fc2_w   = (const float*)d_in[5];
    const float* fc2_b   = (const float*)d_in[6];
    const float* final_w = (const float*)d_in[7];
    const float* final_b = (const float*)d_in[8];
    float* out = (float*)d_out;

    static bool attr_set = false;
    cudaFuncSetAttribute(mma_gemm<0>, cudaFuncAttributeMaxDynamicSharedMemorySize, GEMM_SMEM);
    cudaFuncSetAttribute(mma_gemm<1>, cudaFuncAttributeMaxDynamicSharedMemorySize, GEMM_SMEM);
    cudaFuncSetAttribute(mma_gemm<2>, cudaFuncAttributeMaxDynamicSharedMemorySize, GEMM_SMEM);
    (void)attr_set;

    __nv_bfloat16 *xh, *xl, *w1h, *w1l, *w2h, *w2l, *fwh, *fwl;
    cudaGetSymbolAddress((void**)&xh,  g_xh);
    cudaGetSymbolAddress((void**)&xl,  g_xl);
    cudaGetSymbolAddress((void**)&w1h, g_w1h);
    cudaGetSymbolAddress((void**)&w1l, g_w1l);
    cudaGetSymbolAddress((void**)&w2h, g_w2h);
    cudaGetSymbolAddress((void**)&w2l, g_w2l);
    cudaGetSymbolAddress((void**)&fwh, g_fwh);
    cudaGetSymbolAddress((void**)&fwl, g_fwl);

    zero_kernel<<<1, 32>>>();
    gating_kernel<<<T_/64, 256>>>(xs, Wg, b, out);

    pack_split<<<(T_*D_/4)/256,   256>>>(xs,      xh,  xl,  T_*D_/4);
    pack_split<<<(E_*H_*D_/4)/256, 256>>>(fc1_w,  w1h, w1l, E_*H_*D_/4);
    pack_split<<<(E_*H_*H_/4)/256, 256>>>(fc2_w,  w2h, w2l, E_*H_*H_/4);
    pack_split<<<(O_*H_/4)/256,   256>>>(final_w, fwh, fwl, O_*H_/4);

    dim3 g1(H_/128, MAXR/128, E_);
    mma_gemm<1><<<g1, 256, GEMM_SMEM>>>(fc1_b, nullptr);
    mma_gemm<2><<<g1, 256, GEMM_SMEM>>>(fc2_b, nullptr);
    combine_kernel<<<(B_*(H_/4))/256, 256>>>();
    dim3 gf(O_/128, B_/128);
    mma_gemm<0><<<gf, 256, GEMM_SMEM>>>(final_b, out);
}

// round 5
// speedup vs baseline: 4.4074x; 1.1097x over previous
#include <cuda_runtime.h>
#include <cuda_bf16.h>
#include <math.h>
#include <stdint.h>

// Problem constants
#define S_ 2
#define B_ 2048
#define D_ 1024
#define H_ 2048
#define E_ 8
#define O_ 1024
#define T_ (S_*B_)        // 4096 tokens
#define P_ (T_*2)         // 8192 (token, k) pairs
#define MAXR 4096
#define OUT_OFF ((size_t)B_*O_)

// ---------------- scratch (device globals) ----------------
__device__ __align__(128) __nv_bfloat16 g_xh[(size_t)T_ * D_];
__device__ __align__(128) __nv_bfloat16 g_xl[(size_t)T_ * D_];
__device__ __align__(128) __nv_bfloat16 g_w1h[(size_t)E_ * H_ * D_];
__device__ __align__(128) __nv_bfloat16 g_w1l[(size_t)E_ * H_ * D_];
__device__ __align__(128) __nv_bfloat16 g_w2h[(size_t)E_ * H_ * H_];
__device__ __align__(128) __nv_bfloat16 g_w2l[(size_t)E_ * H_ * H_];
__device__ __align__(128) __nv_bfloat16 g_fwh[(size_t)O_ * H_];
__device__ __align__(128) __nv_bfloat16 g_fwl[(size_t)O_ * H_];
__device__ __align__(128) __nv_bfloat16 g_Hh[(size_t)P_ * H_];
__device__ __align__(128) __nv_bfloat16 g_Hl[(size_t)P_ * H_];
__device__ __align__(128) float         g_Y[(size_t)P_ * H_];
__device__ __align__(128) __nv_bfloat16 g_ch[(size_t)B_ * H_];
__device__ __align__(128) __nv_bfloat16 g_cl[(size_t)B_ * H_];
__device__ __align__(128) float g_gate[P_];
__device__ __align__(128) int   g_list[E_ * MAXR];
__device__ int   g_cnt[E_];

__device__ __forceinline__ uint32_t smem_u32(const void* p) {
    uint32_t a;
    asm("{ .reg .u64 t; cvta.to.shared.u64 t, %1; cvt.u32.u64 %0, t; }" : "=r"(a) : "l"(p));
    return a;
}

#define LDSM4(r0, r1, r2, r3, addr) \
    asm volatile("ldmatrix.sync.aligned.m8n8.x4.shared.b16 {%0,%1,%2,%3}, [%4];" \
        : "=r"(r0), "=r"(r1), "=r"(r2), "=r"(r3) : "r"(addr))

#define MMA16816(d, a, b) \
    asm volatile("mma.sync.aligned.m16n8k16.row.col.f32.bf16.bf16.f32 " \
        "{%0,%1,%2,%3}, {%4,%5,%6,%7}, {%8,%9}, {%0,%1,%2,%3};" \
        : "+f"((d)[0]), "+f"((d)[1]), "+f"((d)[2]), "+f"((d)[3]) \
        : "r"((a)[0]), "r"((a)[1]), "r"((a)[2]), "r"((a)[3]), \
          "r"((b)[0]), "r"((b)[1]))

#define CPA16(dst, src, sz) \
    asm volatile("cp.async.cg.shared.global [%0], [%1], 16, %2;" \
        :: "r"(dst), "l"(src), "r"(sz) : "memory")
#define CPCOMMIT() asm volatile("cp.async.commit_group;" ::: "memory")
#define CPWAIT(n)  asm volatile("cp.async.wait_group %0;" :: "n"(n) : "memory")

// hi/lo bf16 split of 2 packed floats
__device__ __forceinline__ void split2(float a, float b, uint32_t &hi, uint32_t &lo) {
    __nv_bfloat162 h = __floats2bfloat162_rn(a, b);
    float la = a - __low2float(h);
    float lb = b - __high2float(h);
    __nv_bfloat162 l = __floats2bfloat162_rn(la, lb);
    hi = *reinterpret_cast<uint32_t*>(&h);
    lo = *reinterpret_cast<uint32_t*>(&l);
}

// swizzled byte offset within an N-row x 32-col bf16 plane (64B rows)
__device__ __forceinline__ int swoff(int r, int c) {
    return r * 64 + ((c ^ ((r >> 1) & 3)) << 4);
}

__global__ void zero_kernel() {
    if (threadIdx.x < E_) g_cnt[threadIdx.x] = 0;
}

// ---------------- pack fp32 -> bf16 hi/lo planes ----------------
__global__ void pack_split(const float* __restrict__ src,
                           __nv_bfloat16* __restrict__ hi,
                           __nv_bfloat16* __restrict__ lo, int n4) {
    int i = blockIdx.x * blockDim.x + threadIdx.x;
    if (i >= n4) return;
    float4 v = reinterpret_cast<const float4*>(src)[i];
    uint2 h, l;
    split2(v.x, v.y, h.x, l.x);
    split2(v.z, v.w, h.y, l.y);
    reinterpret_cast<uint2*>(hi)[i] = h;
    reinterpret_cast<uint2*>(lo)[i] = l;
}

// ---------------- gating ----------------
__global__ __launch_bounds__(256) void gating_kernel(
        const float* __restrict__ xs, const float* __restrict__ Wg,
        const float* __restrict__ bias, float* __restrict__ out)
{
    __shared__ __align__(16) float ws[E_][D_];
    int tid = threadIdx.x;
    for (int i = tid; i < E_*D_; i += 256) {
        int e = i >> 10, d = i & (D_-1);
        ws[e][d] = Wg[d*E_ + e];
    }
    __syncthreads();
    int warp = tid >> 5, lane = tid & 31;
    for (int tt = 0; tt < 8; ++tt) {
        int t = blockIdx.x * 64 + warp * 8 + tt;
        float acc[E_];
        #pragma unroll
        for (int e = 0; e < E_; ++e) acc[e] = 0.f;
        const float4* xrow = reinterpret_cast<const float4*>(xs + (size_t)t * D_);
        #pragma unroll
        for (int it = 0; it < D_/128; ++it) {
            float4 x = xrow[lane + it*32];
            #pragma unroll
            for (int e = 0; e < E_; ++e) {
                float4 w = reinterpret_cast<const float4*>(ws[e])[lane + it*32];
                acc[e] += x.x*w.x + x.y*w.y + x.z*w.z + x.w*w.w;
            }
        }
        #pragma unroll
        for (int off = 16; off > 0; off >>= 1) {
            #pragma unroll
            for (int e = 0; e < E_; ++e)
                acc[e] += __shfl_xor_sync(0xffffffffu, acc[e], off);
        }
        if (lane == 0) {
            float h[E_];
            #pragma unroll
            for (int e = 0; e < E_; ++e) h[e] = acc[e] + bias[e];
            float m1 = h[0]; int i1 = 0;
            #pragma unroll
            for (int e = 1; e < E_; ++e) if (h[e] > m1) { m1 = h[e]; i1 = e; }
            float m2 = -3.0e38f; int i2 = 0;
            #pragma unroll
            for (int e = 0; e < E_; ++e) if (e != i1 && h[e] > m2) { m2 = h[e]; i2 = e; }
            float pr[E_]; float den = 0.f;
            #pragma unroll
            for (int e = 0; e < E_; ++e) { pr[e] = expf(h[e] - m1); den += pr[e]; }
            float inv = 1.f / den;
            float* ep = out + OUT_OFF + (size_t)t * E_;
            #pragma unroll
            for (int e = 0; e < E_; ++e) ep[e] = pr[e] * inv;
            float l2 = expf(m2 - m1);
            float gd = 1.f + l2;
            g_gate[t*2]     = 1.f / gd;
            g_gate[t*2 + 1] = l2 / gd;
            int pos = atomicAdd(&g_cnt[i1], 1); g_list[i1*MAXR + pos] = t*2;
            pos     = atomicAdd(&g_cnt[i2], 1); g_list[i2*MAXR + pos] = t*2 + 1;
        }
    }
}

// ---- mma.sync split-bf16 GEMM: 512 threads, tile 128x256, BK=32, 4-stage cp.async ----
// Warp grid: 4 (m) x 4 (n); warp tile 32x64.
// MODE 0: final (A=g_ch/l, W=g_fwh/l, C=out,  K=2048, N=1024)
// MODE 1: fc1   (A=g_xh/l by token, W=g_w1h/l, C=g_Hh/g_Hl, K=1024, N=2048, relu)
// MODE 2: fc2   (A=g_Hh/l by pair,  W=g_w2h/l, C=g_Y fp32,  K=2048, N=2048, *gate)
#define PL_A_HI 0
#define PL_A_LO 8192
#define PL_B_HI 16384
#define PL_B_LO 32768
#define STG_BYTES 49152
#define GEMM_SMEM (4 * STG_BYTES)   // 192 KB

template<int MODE>
__global__ __launch_bounds__(512, 1) void mma_gemm(
        const float* __restrict__ biasF, float* __restrict__ Cout)
{
    constexpr int K    = (MODE == 1) ? 1024 : 2048;
    constexpr int NTOT = (MODE == 0) ? 1024 : 2048;
    constexpr int NC   = K / 32;

    const __nv_bfloat16 *Ah_g, *Al_g, *Wh_g, *Wl_g;
    if (MODE == 0) { Ah_g = g_ch; Al_g = g_cl; Wh_g = g_fwh; Wl_g = g_fwl; }
    else if (MODE == 1) { Ah_g = g_xh; Al_g = g_xl; Wh_g = g_w1h; Wl_g = g_w1l; }
    else { Ah_g = g_Hh; Al_g = g_Hl; Wh_g = g_w2h; Wl_g = g_w2l; }

    int e = (MODE == 0) ? 0 : blockIdx.z;
    int cnt;
    const int* lst = nullptr;
    if (MODE == 0) cnt = B_;
    else { cnt = g_cnt[e]; lst = g_list + e * MAXR; }
    int row0 = blockIdx.y * 128;
    if (row0 >= cnt) return;
    int n0blk = blockIdx.x * 256;
    const __nv_bfloat16* Wbh = Wh_g + (size_t)e * NTOT * K;
    const __nv_bfloat16* Wbl = Wl_g + (size_t)e * NTOT * K;
    const float* bb = biasF + (size_t)e * ((MODE == 0) ? 0 : NTOT);

    extern __shared__ unsigned char sm[];
    uint32_t su = smem_u32(sm);

    int tid = threadIdx.x;
    int wid = tid >> 5, lane = tid & 31;
    int warp_m = wid >> 2;        // 0..3 (32 rows each)
    int warp_n = wid & 3;         // 0..3 (64 cols each)

    // ---- cp.async assignment ----
    // A planes: 128 rows x 64B; thread -> row tid>>2, chunk tid&3
    int ar_ld = tid >> 2, ac_ld = tid & 3;
    int gr_ld = row0 + ar_ld;
    uint32_t aSz = (gr_ld < cnt) ? 16u : 0u;
    int aridx;
    if (MODE == 0) aridx = (gr_ld < cnt) ? gr_ld : 0;
    else {
        int p = (gr_ld < cnt) ? lst[gr_ld] : 0;
        aridx = (MODE == 1) ? (p >> 1) : p;
    }
    const __nv_bfloat16* aPh = Ah_g + (size_t)aridx * K + ac_ld * 8;
    const __nv_bfloat16* aPl = Al_g + (size_t)aridx * K + ac_ld * 8;
    int sA = swoff(ar_ld, ac_ld);
    // B planes: 256 rows x 64B; thread -> row tid>>1, chunks (tid&1)*2 + {0,1}
    int br_ld = tid >> 1, bc_ld = (tid & 1) * 2;
    const __nv_bfloat16* bPh = Wbh + (size_t)(n0blk + br_ld) * K + bc_ld * 8;
    const __nv_bfloat16* bPl = Wbl + (size_t)(n0blk + br_ld) * K + bc_ld * 8;
    int sB0 = swoff(br_ld, bc_ld);
    int sB1 = swoff(br_ld, bc_ld + 1);

    // ---- ldmatrix offsets ----
    int aoffs[2][2], boffs[4][2];
    {
        int arr = warp_m * 32 + (lane & 15);
        int achi = lane >> 4;
        #pragma unroll
        for (int t = 0; t < 2; ++t)
            #pragma unroll
            for (int ks = 0; ks < 2; ++ks)
                aoffs[t][ks] = swoff(arr + t * 16, ks * 2 + achi);
        int brr = warp_n * 64 + (lane & 7) + ((lane >> 4) << 3);
        int bchi = (lane >> 3) & 1;
        #pragma unroll
        for (int jj = 0; jj < 4; ++jj)
            #pragma unroll
            for (int ks = 0; ks < 2; ++ks)
                boffs[jj][ks] = swoff(brr + jj * 16, ks * 2 + bchi);
    }

    float acc[2][8][4];
    #pragma unroll
    for (int t = 0; t < 2; ++t)
        #pragma unroll
        for (int j = 0; j < 8; ++j)
            #pragma unroll
            for (int q = 0; q < 4; ++q) acc[t][j][q] = 0.f;

    auto issue = [&](int c) {
        uint32_t sb = su + (c & 3) * STG_BYTES;
        int k0 = c * 32;
        CPA16(sb + PL_A_HI + sA,  aPh + k0, aSz);
        CPA16(sb + PL_A_LO + sA,  aPl + k0, aSz);
        CPA16(sb + PL_B_HI + sB0, bPh + k0, 16u);
        CPA16(sb + PL_B_HI + sB1, bPh + k0 + 8, 16u);
        CPA16(sb + PL_B_LO + sB0, bPl + k0, 16u);
        CPA16(sb + PL_B_LO + sB1, bPl + k0 + 8, 16u);
    };

    issue(0); CPCOMMIT();
    issue(1); CPCOMMIT();
    issue(2); CPCOMMIT();

    for (int c = 0; c < NC; ++c) {
        CPWAIT(2);
        __syncthreads();
        if (c + 3 < NC) { issue(c + 3); CPCOMMIT(); }
        uint32_t base = su + (c & 3) * STG_BYTES;
        #pragma unroll
        for (int ks = 0; ks < 2; ++ks) {
            uint32_t Ah[2][4], Al[2][4], Bf[8][2];
            #pragma unroll
            for (int t = 0; t < 2; ++t) {
                LDSM4(Ah[t][0], Ah[t][1], Ah[t][2], Ah[t][3], base + PL_A_HI + aoffs[t][ks]);
                LDSM4(Al[t][0], Al[t][1], Al[t][2], Al[t][3], base + PL_A_LO + aoffs[t][ks]);
            }
            #pragma unroll
            for (int jj = 0; jj < 4; ++jj)
                LDSM4(Bf[2*jj][0], Bf[2*jj][1], Bf[2*jj+1][0], Bf[2*jj+1][1],
                      base + PL_B_HI + boffs[jj][ks]);
            #pragma unroll
            for (int t = 0; t < 2; ++t)
                #pragma unroll
                for (int j = 0; j < 8; ++j)
                    MMA16816(acc[t][j], Ah[t], Bf[j]);
            #pragma unroll
            for (int t = 0; t < 2; ++t)
                #pragma unroll
                for (int j = 0; j < 8; ++j)
                    MMA16816(acc[t][j], Al[t], Bf[j]);
            #pragma unroll
            for (int jj = 0; jj < 4; ++jj)
                LDSM4(Bf[2*jj][0], Bf[2*jj][1], Bf[2*jj+1][0], Bf[2*jj+1][1],
                      base + PL_B_LO + boffs[jj][ks]);
            #pragma unroll
            for (int t = 0; t < 2; ++t)
                #pragma unroll
                for (int j = 0; j < 8; ++j)
                    MMA16816(acc[t][j], Ah[t], Bf[j]);
        }
    }

    // ---- epilogue ----
    int mwarp = row0 + warp_m * 32;
    #pragma unroll
    for (int t = 0; t < 2; ++t) {
        #pragma unroll
        for (int half = 0; half < 2; ++half) {
            int gr = mwarp + t * 16 + (lane >> 2) + half * 8;
            if (gr >= cnt) continue;
            float gate = 1.f;
            float* crowf = nullptr;
            __nv_bfloat16 *crh = nullptr, *crl = nullptr;
            if (MODE == 0) crowf = Cout + (size_t)gr * O_;
            else {
                int p = lst[gr];
                if (MODE == 1) {
                    crh = g_Hh + (size_t)p * H_;
                    crl = g_Hl + (size_t)p * H_;
                } else {
                    crowf = g_Y + (size_t)p * H_;
                    gate = g_gate[p];
                }
            }
            #pragma unroll
            for (int j = 0; j < 8; ++j) {
                int n = n0blk + warp_n * 64 + j * 8 + (lane & 3) * 2;
                float v0 = acc[t][j][half*2 + 0] + bb[n];
                float v1 = acc[t][j][half*2 + 1] + bb[n + 1];
                if (MODE == 1) {
                    v0 = fmaxf(v0, 0.f); v1 = fmaxf(v1, 0.f);
                    uint32_t h, l;
                    split2(v0, v1, h, l);
                    *reinterpret_cast<uint32_t*>(crh + n) = h;
                    *reinterpret_cast<uint32_t*>(crl + n) = l;
                } else {
                    if (MODE == 2) { v0 *= gate; v1 *= gate; }
                    *reinterpret_cast<float2*>(crowf + n) = make_float2(v0, v1);
                }
            }
        }
    }
}

// ---------------- combine ----------------
__global__ void combine_kernel() {
    int idx = blockIdx.x * blockDim.x + threadIdx.x;
    int b  = idx >> 9;
    int gq = idx & 511;
    const float4* Y = reinterpret_cast<const float4*>(g_Y);
    size_t base0 = ((size_t)(b)      * 2) * (H_/4) + gq;
    size_t base1 = ((size_t)(B_ + b) * 2) * (H_/4) + gq;
    float4 y0 = Y[base0], y1 = Y[base0 + H_/4];
    float4 y2 = Y[base1], y3 = Y[base1 + H_/4];
    float4 o;
    o.x = 0.5f * (y0.x + y1.x + y2.x + y3.x);
    o.y = 0.5f * (y0.y + y1.y + y2.y + y3.y);
    o.z = 0.5f * (y0.z + y1.z + y2.z + y3.z);
    o.w = 0.5f * (y0.w + y1.w + y2.w + y3.w);
    uint2 h, l;
    split2(o.x, o.y, h.x, l.x);
    split2(o.z, o.w, h.y, l.y);
    size_t off = (size_t)b * (H_/4) + gq;
    reinterpret_cast<uint2*>(g_ch)[off] = h;
    reinterpret_cast<uint2*>(g_cl)[off] = l;
}

extern "C" void kernel_launch(void* const* d_in, const int* in_sizes, int n_in,
                              void* d_out, int out_size) {
    const float* xs      = (const float*)d_in[0];
    const float* Wg      = (const float*)d_in[1];
    const float* b       = (const float*)d_in[2];
    const float* fc1_w   = (const float*)d_in[3];
    const float* fc1_b   = (const float*)d_in[4];
    const float* fc2_w   = (const float*)d_in[5];
    const float* fc2_b   = (const float*)d_in[6];
    const float* final_w = (const float*)d_in[7];
    const float* final_b = (const float*)d_in[8];
    float* out = (float*)d_out;

    cudaFuncSetAttribute(mma_gemm<0>, cudaFuncAttributeMaxDynamicSharedMemorySize, GEMM_SMEM);
    cudaFuncSetAttribute(mma_gemm<1>, cudaFuncAttributeMaxDynamicSharedMemorySize, GEMM_SMEM);
    cudaFuncSetAttribute(mma_gemm<2>, cudaFuncAttributeMaxDynamicSharedMemorySize, GEMM_SMEM);

    __nv_bfloat16 *xh, *xl, *w1h, *w1l, *w2h, *w2l, *fwh, *fwl;
    cudaGetSymbolAddress((void**)&xh,  g_xh);
    cudaGetSymbolAddress((void**)&xl,  g_xl);
    cudaGetSymbolAddress((void**)&w1h, g_w1h);
    cudaGetSymbolAddress((void**)&w1l, g_w1l);
    cudaGetSymbolAddress((void**)&w2h, g_w2h);
    cudaGetSymbolAddress((void**)&w2l, g_w2l);
    cudaGetSymbolAddress((void**)&fwh, g_fwh);
    cudaGetSymbolAddress((void**)&fwl, g_fwl);

    zero_kernel<<<1, 32>>>();
    gating_kernel<<<T_/64, 256>>>(xs, Wg, b, out);

    pack_split<<<(T_*D_/4)/256,   256>>>(xs,      xh,  xl,  T_*D_/4);
    pack_split<<<(E_*H_*D_/4)/256, 256>>>(fc1_w,  w1h, w1l, E_*H_*D_/4);
    pack_split<<<(E_*H_*H_/4)/256, 256>>>(fc2_w,  w2h, w2l, E_*H_*H_/4);
    pack_split<<<(O_*H_/4)/256,   256>>>(final_w, fwh, fwl, O_*H_/4);

    dim3 g1(H_/256, MAXR/128, E_);
    mma_gemm<1><<<g1, 512, GEMM_SMEM>>>(fc1_b, nullptr);
    mma_gemm<2><<<g1, 512, GEMM_SMEM>>>(fc2_b, nullptr);
    combine_kernel<<<(B_*(H_/4))/256, 256>>>();
    dim3 gf(O_/256, B_/128);
    mma_gemm<0><<<gf, 512, GEMM_SMEM>>>(final_b, out);
}

// round 6
// speedup vs baseline: 9.1621x; 2.0788x over previous
#include <cuda_runtime.h>
#include <cuda_bf16.h>
#include <cuda_fp16.h>
#include <math.h>
#include <stdint.h>

// Problem constants
#define S_ 2
#define B_ 2048
#define D_ 1024
#define H_ 2048
#define E_ 8
#define O_ 1024
#define T_ (S_*B_)        // 4096 tokens
#define P_ (T_*2)         // 8192 (token, k) pairs
#define MAXR 4096
#define OUT_OFF ((size_t)B_*O_)

// ---------------- scratch (device globals) ----------------
__device__ __align__(128) __half g_xh[(size_t)T_ * D_];
__device__ __align__(128) __half g_w1h[(size_t)E_ * H_ * D_];
__device__ __align__(128) __half g_w2h[(size_t)E_ * H_ * H_];
__device__ __align__(128) __half g_fwh[(size_t)O_ * H_];
__device__ __align__(128) __half g_Hh[(size_t)P_ * H_];
__device__ __align__(128) float  g_Y[(size_t)P_ * H_];
__device__ __align__(128) __half g_ch[(size_t)B_ * H_];
__device__ __align__(128) float g_gate[P_];
__device__ __align__(128) int   g_list[E_ * MAXR];
__device__ int   g_cnt[E_];

__device__ __forceinline__ uint32_t smem_u32(const void* p) {
    uint32_t a;
    asm("{ .reg .u64 t; cvta.to.shared.u64 t, %1; cvt.u32.u64 %0, t; }" : "=r"(a) : "l"(p));
    return a;
}

#define LDSM4(r0, r1, r2, r3, addr) \
    asm volatile("ldmatrix.sync.aligned.m8n8.x4.shared.b16 {%0,%1,%2,%3}, [%4];" \
        : "=r"(r0), "=r"(r1), "=r"(r2), "=r"(r3) : "r"(addr))

#define MMA16816(d, a, b) \
    asm volatile("mma.sync.aligned.m16n8k16.row.col.f32.f16.f16.f32 " \
        "{%0,%1,%2,%3}, {%4,%5,%6,%7}, {%8,%9}, {%0,%1,%2,%3};" \
        : "+f"((d)[0]), "+f"((d)[1]), "+f"((d)[2]), "+f"((d)[3]) \
        : "r"((a)[0]), "r"((a)[1]), "r"((a)[2]), "r"((a)[3]), \
          "r"((b)[0]), "r"((b)[1]))

#define CPA16(dst, src, sz) \
    asm volatile("cp.async.cg.shared.global [%0], [%1], 16, %2;" \
        :: "r"(dst), "l"(src), "r"(sz) : "memory")
#define CPCOMMIT() asm volatile("cp.async.commit_group;" ::: "memory")
#define CPWAIT(n)  asm volatile("cp.async.wait_group %0;" :: "n"(n) : "memory")

// swizzled byte offset within an N-row x 32-col fp16 plane (64B rows)
__device__ __forceinline__ int swoff(int r, int c) {
    return r * 64 + ((c ^ ((r >> 1) & 3)) << 4);
}

__global__ void zero_kernel() {
    if (threadIdx.x < E_) g_cnt[threadIdx.x] = 0;
}

// ---------------- pack fp32 -> fp16 ----------------
__global__ void pack_half(const float* __restrict__ src,
                          __half* __restrict__ dst, int n4) {
    int i = blockIdx.x * blockDim.x + threadIdx.x;
    if (i >= n4) return;
    float4 v = reinterpret_cast<const float4*>(src)[i];
    __half2 a = __floats2half2_rn(v.x, v.y);
    __half2 b = __floats2half2_rn(v.z, v.w);
    uint2 o;
    o.x = *reinterpret_cast<uint32_t*>(&a);
    o.y = *reinterpret_cast<uint32_t*>(&b);
    reinterpret_cast<uint2*>(dst)[i] = o;
}

// ---------------- gating ----------------
__global__ __launch_bounds__(256) void gating_kernel(
        const float* __restrict__ xs, const float* __restrict__ Wg,
        const float* __restrict__ bias, float* __restrict__ out)
{
    __shared__ __align__(16) float ws[E_][D_];
    int tid = threadIdx.x;
    for (int i = tid; i < E_*D_; i += 256) {
        int e = i >> 10, d = i & (D_-1);
        ws[e][d] = Wg[d*E_ + e];
    }
    __syncthreads();
    int warp = tid >> 5, lane = tid & 31;
    for (int tt = 0; tt < 8; ++tt) {
        int t = blockIdx.x * 64 + warp * 8 + tt;
        float acc[E_];
        #pragma unroll
        for (int e = 0; e < E_; ++e) acc[e] = 0.f;
        const float4* xrow = reinterpret_cast<const float4*>(xs + (size_t)t * D_);
        #pragma unroll
        for (int it = 0; it < D_/128; ++it) {
            float4 x = xrow[lane + it*32];
            #pragma unroll
            for (int e = 0; e < E_; ++e) {
                float4 w = reinterpret_cast<const float4*>(ws[e])[lane + it*32];
                acc[e] += x.x*w.x + x.y*w.y + x.z*w.z + x.w*w.w;
            }
        }
        #pragma unroll
        for (int off = 16; off > 0; off >>= 1) {
            #pragma unroll
            for (int e = 0; e < E_; ++e)
                acc[e] += __shfl_xor_sync(0xffffffffu, acc[e], off);
        }
        if (lane == 0) {
            float h[E_];
            #pragma unroll
            for (int e = 0; e < E_; ++e) h[e] = acc[e] + bias[e];
            float m1 = h[0]; int i1 = 0;
            #pragma unroll
            for (int e = 1; e < E_; ++e) if (h[e] > m1) { m1 = h[e]; i1 = e; }
            float m2 = -3.0e38f; int i2 = 0;
            #pragma unroll
            for (int e = 0; e < E_; ++e) if (e != i1 && h[e] > m2) { m2 = h[e]; i2 = e; }
            float pr[E_]; float den = 0.f;
            #pragma unroll
            for (int e = 0; e < E_; ++e) { pr[e] = expf(h[e] - m1); den += pr[e]; }
            float inv = 1.f / den;
            float* ep = out + OUT_OFF + (size_t)t * E_;
            #pragma unroll
            for (int e = 0; e < E_; ++e) ep[e] = pr[e] * inv;
            float l2 = expf(m2 - m1);
            float gd = 1.f + l2;
            g_gate[t*2]     = 1.f / gd;
            g_gate[t*2 + 1] = l2 / gd;
            int pos = atomicAdd(&g_cnt[i1], 1); g_list[i1*MAXR + pos] = t*2;
            pos     = atomicAdd(&g_cnt[i2], 1); g_list[i2*MAXR + pos] = t*2 + 1;
        }
    }
}

// ---- fp16 mma.sync GEMM: 512 threads, tile BMx256, BK=32, 6-stage cp.async ----
// Warp grid: 4 (m) x 4 (n); warp tile (BM/4)x64.
// MODE 0: final (A=g_ch, W=g_fwh, C=out,  K=2048, N=1024, BM=64)
// MODE 1: fc1   (A=g_xh by token, W=g_w1h, C=g_Hh fp16, K=1024, N=2048, relu, BM=128)
// MODE 2: fc2   (A=g_Hh by pair,  W=g_w2h, C=g_Y fp32,  K=2048, N=2048, *gate, BM=128)
#define NSTG 6

template<int MODE>
__global__ __launch_bounds__(512, 1) void mma_gemm(
        const float* __restrict__ biasF, float* __restrict__ Cout)
{
    constexpr int K    = (MODE == 1) ? 1024 : 2048;
    constexpr int NTOT = (MODE == 0) ? 1024 : 2048;
    constexpr int NC   = K / 32;
    constexpr int BM   = (MODE == 0) ? 64 : 128;
    constexpr int TA   = BM / 64;                 // A frags per warp (1 or 2)
    constexpr int ABYTES = BM * 64;               // A plane bytes per stage
    constexpr int STG  = ABYTES + 256 * 64;       // stage bytes (A + B)

    const __half *Ah_g, *Wh_g;
    if (MODE == 0)      { Ah_g = g_ch;  Wh_g = g_fwh; }
    else if (MODE == 1) { Ah_g = g_xh;  Wh_g = g_w1h; }
    else                { Ah_g = g_Hh;  Wh_g = g_w2h; }

    int e = (MODE == 0) ? 0 : blockIdx.z;
    int cnt;
    const int* lst = nullptr;
    if (MODE == 0) cnt = B_;
    else { cnt = g_cnt[e]; lst = g_list + e * MAXR; }
    int row0 = blockIdx.y * BM;
    if (row0 >= cnt) return;
    int n0blk = blockIdx.x * 256;
    const __half* Wb = Wh_g + (size_t)e * NTOT * K;
    const float* bb = biasF + (size_t)e * ((MODE == 0) ? 0 : NTOT);

    extern __shared__ unsigned char sm[];
    uint32_t su = smem_u32(sm);

    int tid = threadIdx.x;
    int wid = tid >> 5, lane = tid & 31;
    int warp_m = wid >> 2;        // 0..3
    int warp_n = wid & 3;         // 0..3 (64 cols each)

    // ---- cp.async assignment ----
    // A plane: BM rows x 64B -> BM*4 chunks
    int ar_ld = tid >> 2, ac_ld = tid & 3;
    bool aactive = ar_ld < BM;
    int gr_ld = row0 + ar_ld;
    uint32_t aSz = (aactive && gr_ld < cnt) ? 16u : 0u;
    int aridx = 0;
    if (aactive) {
        if (MODE == 0) aridx = (gr_ld < cnt) ? gr_ld : 0;
        else {
            int p = (gr_ld < cnt) ? lst[gr_ld] : 0;
            aridx = (MODE == 1) ? (p >> 1) : p;
        }
    }
    const __half* aP = Ah_g + (size_t)aridx * K + ac_ld * 8;
    int sA = swoff(ar_ld, ac_ld);
    // B plane: 256 rows x 64B -> 1024 chunks, 2 per thread
    int br_ld = tid >> 1, bc_ld = (tid & 1) * 2;
    const __half* bP = Wb + (size_t)(n0blk + br_ld) * K + bc_ld * 8;
    int sB0 = swoff(br_ld, bc_ld);
    int sB1 = swoff(br_ld, bc_ld + 1);

    // ---- ldmatrix offsets ----
    int aoffs[TA][2], boffs[4][2];
    {
        int arr = warp_m * (BM/4) + (lane & 15);
        int achi = lane >> 4;
        #pragma unroll
        for (int t = 0; t < TA; ++t)
            #pragma unroll
            for (int ks = 0; ks < 2; ++ks)
                aoffs[t][ks] = swoff(arr + t * 16, ks * 2 + achi);
        int brr = warp_n * 64 + (lane & 7) + ((lane >> 4) << 3);
        int bchi = (lane >> 3) & 1;
        #pragma unroll
        for (int jj = 0; jj < 4; ++jj)
            #pragma unroll
            for (int ks = 0; ks < 2; ++ks)
                boffs[jj][ks] = swoff(brr + jj * 16, ks * 2 + bchi);
    }

    float acc[TA][8][4];
    #pragma unroll
    for (int t = 0; t < TA; ++t)
        #pragma unroll
        for (int j = 0; j < 8; ++j)
            #pragma unroll
            for (int q = 0; q < 4; ++q) acc[t][j][q] = 0.f;

    auto issue = [&](int c) {
        uint32_t sb = su + (c % NSTG) * STG;
        int k0 = c * 32;
        if (aactive) CPA16(sb + sA, aP + k0, aSz);
        CPA16(sb + ABYTES + sB0, bP + k0, 16u);
        CPA16(sb + ABYTES + sB1, bP + k0 + 8, 16u);
    };

    #pragma unroll
    for (int c = 0; c < NSTG - 1; ++c) { issue(c); CPCOMMIT(); }

    for (int c = 0; c < NC; ++c) {
        CPWAIT(NSTG - 2);
        __syncthreads();
        if (c + NSTG - 1 < NC) { issue(c + NSTG - 1); CPCOMMIT(); }
        uint32_t base = su + (c % NSTG) * STG;
        #pragma unroll
        for (int ks = 0; ks < 2; ++ks) {
            uint32_t Af[TA][4], Bf[8][2];
            #pragma unroll
            for (int t = 0; t < TA; ++t)
                LDSM4(Af[t][0], Af[t][1], Af[t][2], Af[t][3], base + aoffs[t][ks]);
            #pragma unroll
            for (int jj = 0; jj < 4; ++jj)
                LDSM4(Bf[2*jj][0], Bf[2*jj][1], Bf[2*jj+1][0], Bf[2*jj+1][1],
                      base + ABYTES + boffs[jj][ks]);
            #pragma unroll
            for (int t = 0; t < TA; ++t)
                #pragma unroll
                for (int j = 0; j < 8; ++j)
                    MMA16816(acc[t][j], Af[t], Bf[j]);
        }
        __syncthreads();
    }

    // ---- epilogue ----
    int mwarp = row0 + warp_m * (BM/4);
    #pragma unroll
    for (int t = 0; t < TA; ++t) {
        #pragma unroll
        for (int half = 0; half < 2; ++half) {
            int gr = mwarp + t * 16 + (lane >> 2) + half * 8;
            if (gr >= cnt) continue;
            float gate = 1.f;
            float* crowf = nullptr;
            __half* crh = nullptr;
            if (MODE == 0) crowf = Cout + (size_t)gr * O_;
            else {
                int p = lst[gr];
                if (MODE == 1) crh = g_Hh + (size_t)p * H_;
                else { crowf = g_Y + (size_t)p * H_; gate = g_gate[p]; }
            }
            #pragma unroll
            for (int j = 0; j < 8; ++j) {
                int n = n0blk + warp_n * 64 + j * 8 + (lane & 3) * 2;
                float v0 = acc[t][j][half*2 + 0] + bb[n];
                float v1 = acc[t][j][half*2 + 1] + bb[n + 1];
                if (MODE == 1) {
                    v0 = fmaxf(v0, 0.f); v1 = fmaxf(v1, 0.f);
                    __half2 hv = __floats2half2_rn(v0, v1);
                    *reinterpret_cast<uint32_t*>(crh + n) = *reinterpret_cast<uint32_t*>(&hv);
                } else {
                    if (MODE == 2) { v0 *= gate; v1 *= gate; }
                    *reinterpret_cast<float2*>(crowf + n) = make_float2(v0, v1);
                }
            }
        }
    }
}

// ---------------- combine: sum 4 pair rows, /S, to fp16 ----------------
__global__ void combine_kernel() {
    int idx = blockIdx.x * blockDim.x + threadIdx.x;
    int b  = idx >> 9;
    int gq = idx & 511;
    const float4* Y = reinterpret_cast<const float4*>(g_Y);
    size_t base0 = ((size_t)(b)      * 2) * (H_/4) + gq;
    size_t base1 = ((size_t)(B_ + b) * 2) * (H_/4) + gq;
    float4 y0 = Y[base0], y1 = Y[base0 + H_/4];
    float4 y2 = Y[base1], y3 = Y[base1 + H_/4];
    float4 o;
    o.x = 0.5f * (y0.x + y1.x + y2.x + y3.x);
    o.y = 0.5f * (y0.y + y1.y + y2.y + y3.y);
    o.z = 0.5f * (y0.z + y1.z + y2.z + y3.z);
    o.w = 0.5f * (y0.w + y1.w + y2.w + y3.w);
    __half2 a = __floats2half2_rn(o.x, o.y);
    __half2 c = __floats2half2_rn(o.z, o.w);
    uint2 pk;
    pk.x = *reinterpret_cast<uint32_t*>(&a);
    pk.y = *reinterpret_cast<uint32_t*>(&c);
    reinterpret_cast<uint2*>(g_ch)[(size_t)b * (H_/4) + gq] = pk;
}

extern "C" void kernel_launch(void* const* d_in, const int* in_sizes, int n_in,
                              void* d_out, int out_size) {
    const float* xs      = (const float*)d_in[0];
    const float* Wg      = (const float*)d_in[1];
    const float* b       = (const float*)d_in[2];
    const float* fc1_w   = (const float*)d_in[3];
    const float* fc1_b   = (const float*)d_in[4];
    const float* fc2_w   = (const float*)d_in[5];
    const float* fc2_b   = (const float*)d_in[6];
    const float* final_w = (const float*)d_in[7];
    const float* final_b = (const float*)d_in[8];
    float* out = (float*)d_out;

    constexpr int SMEM12 = NSTG * (128*64 + 256*64);  // 144 KB
    constexpr int SMEM0  = NSTG * ( 64*64 + 256*64);  // 120 KB
    cudaFuncSetAttribute(mma_gemm<0>, cudaFuncAttributeMaxDynamicSharedMemorySize, SMEM0);
    cudaFuncSetAttribute(mma_gemm<1>, cudaFuncAttributeMaxDynamicSharedMemorySize, SMEM12);
    cudaFuncSetAttribute(mma_gemm<2>, cudaFuncAttributeMaxDynamicSharedMemorySize, SMEM12);

    __half *xh, *w1h, *w2h, *fwh;
    cudaGetSymbolAddress((void**)&xh,  g_xh);
    cudaGetSymbolAddress((void**)&w1h, g_w1h);
    cudaGetSymbolAddress((void**)&w2h, g_w2h);
    cudaGetSymbolAddress((void**)&fwh, g_fwh);

    zero_kernel<<<1, 32>>>();
    gating_kernel<<<T_/64, 256>>>(xs, Wg, b, out);

    pack_half<<<(T_*D_/4)/256,    256>>>(xs,      xh,  T_*D_/4);
    pack_half<<<(E_*H_*D_/4)/256, 256>>>(fc1_w,   w1h, E_*H_*D_/4);
    pack_half<<<(E_*H_*H_/4)/256, 256>>>(fc2_w,   w2h, E_*H_*H_/4);
    pack_half<<<(O_*H_/4)/256,    256>>>(final_w, fwh, O_*H_/4);

    dim3 g1(H_/256, MAXR/128, E_);
    mma_gemm<1><<<g1, 512, SMEM12>>>(fc1_b, nullptr);
    mma_gemm<2><<<g1, 512, SMEM12>>>(fc2_b, nullptr);
    combine_kernel<<<(B_*(H_/4))/256, 256>>>();
    dim3 gf(O_/256, B_/64);
    mma_gemm<0><<<gf, 512, SMEM0>>>(final_b, out);
}

// round 7
// speedup vs baseline: 9.3042x; 1.0155x over previous
#include <cuda_runtime.h>
#include <cuda_bf16.h>
#include <cuda_fp16.h>
#include <math.h>
#include <stdint.h>

// Problem constants
#define S_ 2
#define B_ 2048
#define D_ 1024
#define H_ 2048
#define E_ 8
#define O_ 1024
#define T_ (S_*B_)        // 4096 tokens
#define P_ (T_*2)         // 8192 (token, k) pairs
#define MAXR 4096
#define OUT_OFF ((size_t)B_*O_)

// ---------------- scratch (device globals) ----------------
__device__ __align__(128) __half g_xh[(size_t)T_ * D_];
__device__ __align__(128) __half g_w1h[(size_t)E_ * H_ * D_];
__device__ __align__(128) __half g_w2h[(size_t)E_ * H_ * H_];
__device__ __align__(128) __half g_fwh[(size_t)O_ * H_];
__device__ __align__(128) __half g_Hh[(size_t)P_ * H_];
__device__ __align__(128) float  g_Y[(size_t)P_ * H_];
__device__ __align__(128) __half g_ch[(size_t)B_ * H_];
__device__ __align__(128) float g_gate[P_];
__device__ __align__(128) int   g_list[E_ * MAXR];
__device__ int   g_cnt[E_];

__device__ __forceinline__ uint32_t smem_u32(const void* p) {
    uint32_t a;
    asm("{ .reg .u64 t; cvta.to.shared.u64 t, %1; cvt.u32.u64 %0, t; }" : "=r"(a) : "l"(p));
    return a;
}

#define LDSM4(r0, r1, r2, r3, addr) \
    asm volatile("ldmatrix.sync.aligned.m8n8.x4.shared.b16 {%0,%1,%2,%3}, [%4];" \
        : "=r"(r0), "=r"(r1), "=r"(r2), "=r"(r3) : "r"(addr))

#define MMA16816(d, a, b) \
    asm volatile("mma.sync.aligned.m16n8k16.row.col.f32.f16.f16.f32 " \
        "{%0,%1,%2,%3}, {%4,%5,%6,%7}, {%8,%9}, {%0,%1,%2,%3};" \
        : "+f"((d)[0]), "+f"((d)[1]), "+f"((d)[2]), "+f"((d)[3]) \
        : "r"((a)[0]), "r"((a)[1]), "r"((a)[2]), "r"((a)[3]), \
          "r"((b)[0]), "r"((b)[1]))

#define CPA16(dst, src, sz) \
    asm volatile("cp.async.cg.shared.global [%0], [%1], 16, %2;" \
        :: "r"(dst), "l"(src), "r"(sz) : "memory")
#define CPCOMMIT() asm volatile("cp.async.commit_group;" ::: "memory")
#define CPWAIT(n)  asm volatile("cp.async.wait_group %0;" :: "n"(n) : "memory")

// swizzled byte offset within an N-row x 32-col fp16 plane (64B rows)
__device__ __forceinline__ int swoff(int r, int c) {
    return r * 64 + ((c ^ ((r >> 1) & 3)) << 4);
}

__global__ void zero_kernel() {
    if (threadIdx.x < E_) g_cnt[threadIdx.x] = 0;
}

// ---------------- pack fp32 -> fp16 ----------------
__global__ void pack_half(const float* __restrict__ src,
                          __half* __restrict__ dst, int n4) {
    int i = blockIdx.x * blockDim.x + threadIdx.x;
    if (i >= n4) return;
    float4 v = reinterpret_cast<const float4*>(src)[i];
    __half2 a = __floats2half2_rn(v.x, v.y);
    __half2 b = __floats2half2_rn(v.z, v.w);
    uint2 o;
    o.x = *reinterpret_cast<uint32_t*>(&a);
    o.y = *reinterpret_cast<uint32_t*>(&b);
    reinterpret_cast<uint2*>(dst)[i] = o;
}

// ---------------- gating ----------------
__global__ __launch_bounds__(256) void gating_kernel(
        const float* __restrict__ xs, const float* __restrict__ Wg,
        const float* __restrict__ bias, float* __restrict__ out)
{
    __shared__ __align__(16) float ws[E_][D_];
    int tid = threadIdx.x;
    for (int i = tid; i < E_*D_; i += 256) {
        int e = i >> 10, d = i & (D_-1);
        ws[e][d] = Wg[d*E_ + e];
    }
    __syncthreads();
    int warp = tid >> 5, lane = tid & 31;
    for (int tt = 0; tt < 8; ++tt) {
        int t = blockIdx.x * 64 + warp * 8 + tt;
        float acc[E_];
        #pragma unroll
        for (int e = 0; e < E_; ++e) acc[e] = 0.f;
        const float4* xrow = reinterpret_cast<const float4*>(xs + (size_t)t * D_);
        #pragma unroll
        for (int it = 0; it < D_/128; ++it) {
            float4 x = xrow[lane + it*32];
            #pragma unroll
            for (int e = 0; e < E_; ++e) {
                float4 w = reinterpret_cast<const float4*>(ws[e])[lane + it*32];
                acc[e] += x.x*w.x + x.y*w.y + x.z*w.z + x.w*w.w;
            }
        }
        #pragma unroll
        for (int off = 16; off > 0; off >>= 1) {
            #pragma unroll
            for (int e = 0; e < E_; ++e)
                acc[e] += __shfl_xor_sync(0xffffffffu, acc[e], off);
        }
        if (lane == 0) {
            float h[E_];
            #pragma unroll
            for (int e = 0; e < E_; ++e) h[e] = acc[e] + bias[e];
            float m1 = h[0]; int i1 = 0;
            #pragma unroll
            for (int e = 1; e < E_; ++e) if (h[e] > m1) { m1 = h[e]; i1 = e; }
            float m2 = -3.0e38f; int i2 = 0;
            #pragma unroll
            for (int e = 0; e < E_; ++e) if (e != i1 && h[e] > m2) { m2 = h[e]; i2 = e; }
            float pr[E_]; float den = 0.f;
            #pragma unroll
            for (int e = 0; e < E_; ++e) { pr[e] = expf(h[e] - m1); den += pr[e]; }
            float inv = 1.f / den;
            float* ep = out + OUT_OFF + (size_t)t * E_;
            #pragma unroll
            for (int e = 0; e < E_; ++e) ep[e] = pr[e] * inv;
            float l2 = expf(m2 - m1);
            float gd = 1.f + l2;
            g_gate[t*2]     = 1.f / gd;
            g_gate[t*2 + 1] = l2 / gd;
            int pos = atomicAdd(&g_cnt[i1], 1); g_list[i1*MAXR + pos] = t*2;
            pos     = atomicAdd(&g_cnt[i2], 1); g_list[i2*MAXR + pos] = t*2 + 1;
        }
    }
}

// ---- fp16 mma.sync GEMM: 256 threads, tile 128x128, BK=32, 5-stage, 2 CTA/SM ----
// Warp grid: 4 (m) x 2 (n); warp tile 32x64.
// MODE 0: final (A=g_ch, W=g_fwh, C=out,  K=2048, N=1024)
// MODE 1: fc1   (A=g_xh by token, W=g_w1h, C=g_Hh fp16, K=1024, N=2048, relu)
// MODE 2: fc2   (A=g_Hh by pair,  W=g_w2h, C=g_Y fp32,  K=2048, N=2048, *gate)
#define NSTG 5
#define STG_BYTES 16384       // A 8KB + B 8KB
#define GEMM_SMEM (NSTG * STG_BYTES)   // 80 KB

template<int MODE>
__global__ __launch_bounds__(256, 2) void mma_gemm(
        const float* __restrict__ biasF, float* __restrict__ Cout)
{
    constexpr int K    = (MODE == 1) ? 1024 : 2048;
    constexpr int NTOT = (MODE == 0) ? 1024 : 2048;
    constexpr int NC   = K / 32;

    const __half *Ah_g, *Wh_g;
    if (MODE == 0)      { Ah_g = g_ch;  Wh_g = g_fwh; }
    else if (MODE == 1) { Ah_g = g_xh;  Wh_g = g_w1h; }
    else                { Ah_g = g_Hh;  Wh_g = g_w2h; }

    int e = (MODE == 0) ? 0 : blockIdx.z;
    int cnt;
    const int* lst = nullptr;
    if (MODE == 0) cnt = B_;
    else { cnt = g_cnt[e]; lst = g_list + e * MAXR; }
    int row0 = blockIdx.y * 128;
    if (row0 >= cnt) return;
    int n0blk = blockIdx.x * 128;
    const __half* Wb = Wh_g + (size_t)e * NTOT * K;
    const float* bb = biasF + (size_t)e * ((MODE == 0) ? 0 : NTOT);

    extern __shared__ unsigned char sm[];
    uint32_t su = smem_u32(sm);

    int tid = threadIdx.x;
    int wid = tid >> 5, lane = tid & 31;
    int warp_m = wid >> 1;        // 0..3 (32 rows each)
    int warp_n = wid & 1;         // 0..1 (64 cols each)

    // ---- cp.async assignment: 2 A chunks + 2 B chunks per thread ----
    int r_ld = tid >> 1;                  // 0..127
    int c_ld = (tid & 1) * 2;             // 0 or 2
    int gr_ld = row0 + r_ld;
    uint32_t aSz = (gr_ld < cnt) ? 16u : 0u;
    int aridx;
    if (MODE == 0) aridx = (gr_ld < cnt) ? gr_ld : 0;
    else {
        int p = (gr_ld < cnt) ? lst[gr_ld] : 0;
        aridx = (MODE == 1) ? (p >> 1) : p;
    }
    const __half* aP = Ah_g + (size_t)aridx * K + c_ld * 8;
    const __half* bP = Wb + (size_t)(n0blk + r_ld) * K + c_ld * 8;
    int sA0 = swoff(r_ld, c_ld),     sA1 = swoff(r_ld, c_ld + 1);

    // ---- ldmatrix offsets ----
    int aoffs[2][2], boffs[4][2];
    {
        int arr = warp_m * 32 + (lane & 15);
        int achi = lane >> 4;
        #pragma unroll
        for (int t = 0; t < 2; ++t)
            #pragma unroll
            for (int ks = 0; ks < 2; ++ks)
                aoffs[t][ks] = swoff(arr + t * 16, ks * 2 + achi);
        int brr = warp_n * 64 + (lane & 7) + ((lane >> 4) << 3);
        int bchi = (lane >> 3) & 1;
        #pragma unroll
        for (int jj = 0; jj < 4; ++jj)
            #pragma unroll
            for (int ks = 0; ks < 2; ++ks)
                boffs[jj][ks] = swoff(brr + jj * 16, ks * 2 + bchi);
    }

    float acc[2][8][4];
    #pragma unroll
    for (int t = 0; t < 2; ++t)
        #pragma unroll
        for (int j = 0; j < 8; ++j)
            #pragma unroll
            for (int q = 0; q < 4; ++q) acc[t][j][q] = 0.f;

    auto issue = [&](int c) {
        uint32_t sb = su + (c % NSTG) * STG_BYTES;
        int k0 = c * 32;
        CPA16(sb + sA0, aP + k0, aSz);
        CPA16(sb + sA1, aP + k0 + 8, aSz);
        CPA16(sb + 8192 + sA0, bP + k0, 16u);
        CPA16(sb + 8192 + sA1, bP + k0 + 8, 16u);
    };

    #pragma unroll
    for (int c = 0; c < NSTG - 1; ++c) { issue(c); CPCOMMIT(); }

    for (int c = 0; c < NC; ++c) {
        CPWAIT(NSTG - 2);
        __syncthreads();
        if (c + NSTG - 1 < NC) { issue(c + NSTG - 1); CPCOMMIT(); }
        uint32_t base = su + (c % NSTG) * STG_BYTES;
        #pragma unroll
        for (int ks = 0; ks < 2; ++ks) {
            uint32_t Af[2][4], Bf[8][2];
            #pragma unroll
            for (int t = 0; t < 2; ++t)
                LDSM4(Af[t][0], Af[t][1], Af[t][2], Af[t][3], base + aoffs[t][ks]);
            #pragma unroll
            for (int jj = 0; jj < 4; ++jj)
                LDSM4(Bf[2*jj][0], Bf[2*jj][1], Bf[2*jj+1][0], Bf[2*jj+1][1],
                      base + 8192 + boffs[jj][ks]);
            #pragma unroll
            for (int t = 0; t < 2; ++t)
                #pragma unroll
                for (int j = 0; j < 8; ++j)
                    MMA16816(acc[t][j], Af[t], Bf[j]);
        }
    }

    // ---- epilogue ----
    int mwarp = row0 + warp_m * 32;
    #pragma unroll
    for (int t = 0; t < 2; ++t) {
        #pragma unroll
        for (int half = 0; half < 2; ++half) {
            int gr = mwarp + t * 16 + (lane >> 2) + half * 8;
            if (gr >= cnt) continue;
            float gate = 1.f;
            float* crowf = nullptr;
            __half* crh = nullptr;
            if (MODE == 0) crowf = Cout + (size_t)gr * O_;
            else {
                int p = lst[gr];
                if (MODE == 1) crh = g_Hh + (size_t)p * H_;
                else { crowf = g_Y + (size_t)p * H_; gate = g_gate[p]; }
            }
            #pragma unroll
            for (int j = 0; j < 8; ++j) {
                int n = n0blk + warp_n * 64 + j * 8 + (lane & 3) * 2;
                float v0 = acc[t][j][half*2 + 0] + bb[n];
                float v1 = acc[t][j][half*2 + 1] + bb[n + 1];
                if (MODE == 1) {
                    v0 = fmaxf(v0, 0.f); v1 = fmaxf(v1, 0.f);
                    __half2 hv = __floats2half2_rn(v0, v1);
                    *reinterpret_cast<uint32_t*>(crh + n) = *reinterpret_cast<uint32_t*>(&hv);
                } else {
                    if (MODE == 2) { v0 *= gate; v1 *= gate; }
                    *reinterpret_cast<float2*>(crowf + n) = make_float2(v0, v1);
                }
            }
        }
    }
}

// ---------------- combine: sum 4 pair rows, /S, to fp16 ----------------
__global__ void combine_kernel() {
    int idx = blockIdx.x * blockDim.x + threadIdx.x;
    int b  = idx >> 9;
    int gq = idx & 511;
    const float4* Y = reinterpret_cast<const float4*>(g_Y);
    size_t base0 = ((size_t)(b)      * 2) * (H_/4) + gq;
    size_t base1 = ((size_t)(B_ + b) * 2) * (H_/4) + gq;
    float4 y0 = Y[base0], y1 = Y[base0 + H_/4];
    float4 y2 = Y[base1], y3 = Y[base1 + H_/4];
    float4 o;
    o.x = 0.5f * (y0.x + y1.x + y2.x + y3.x);
    o.y = 0.5f * (y0.y + y1.y + y2.y + y3.y);
    o.z = 0.5f * (y0.z + y1.z + y2.z + y3.z);
    o.w = 0.5f * (y0.w + y1.w + y2.w + y3.w);
    __half2 a = __floats2half2_rn(o.x, o.y);
    __half2 c = __floats2half2_rn(o.z, o.w);
    uint2 pk;
    pk.x = *reinterpret_cast<uint32_t*>(&a);
    pk.y = *reinterpret_cast<uint32_t*>(&c);
    reinterpret_cast<uint2*>(g_ch)[(size_t)b * (H_/4) + gq] = pk;
}

extern "C" void kernel_launch(void* const* d_in, const int* in_sizes, int n_in,
                              void* d_out, int out_size) {
    const float* xs      = (const float*)d_in[0];
    const float* Wg      = (const float*)d_in[1];
    const float* b       = (const float*)d_in[2];
    const float* fc1_w   = (const float*)d_in[3];
    const float* fc1_b   = (const float*)d_in[4];
    const float* fc2_w   = (const float*)d_in[5];
    const float* fc2_b   = (const float*)d_in[6];
    const float* final_w = (const float*)d_in[7];
    const float* final_b = (const float*)d_in[8];
    float* out = (float*)d_out;

    cudaFuncSetAttribute(mma_gemm<0>, cudaFuncAttributeMaxDynamicSharedMemorySize, GEMM_SMEM);
    cudaFuncSetAttribute(mma_gemm<1>, cudaFuncAttributeMaxDynamicSharedMemorySize, GEMM_SMEM);
    cudaFuncSetAttribute(mma_gemm<2>, cudaFuncAttributeMaxDynamicSharedMemorySize, GEMM_SMEM);

    __half *xh, *w1h, *w2h, *fwh;
    cudaGetSymbolAddress((void**)&xh,  g_xh);
    cudaGetSymbolAddress((void**)&w1h, g_w1h);
    cudaGetSymbolAddress((void**)&w2h, g_w2h);
    cudaGetSymbolAddress((void**)&fwh, g_fwh);

    zero_kernel<<<1, 32>>>();
    gating_kernel<<<T_/64, 256>>>(xs, Wg, b, out);

    pack_half<<<(T_*D_/4)/256,    256>>>(xs,      xh,  T_*D_/4);
    pack_half<<<(E_*H_*D_/4)/256, 256>>>(fc1_w,   w1h, E_*H_*D_/4);
    pack_half<<<(E_*H_*H_/4)/256, 256>>>(fc2_w,   w2h, E_*H_*H_/4);
    pack_half<<<(O_*H_/4)/256,    256>>>(final_w, fwh, O_*H_/4);

    dim3 g1(H_/128, MAXR/128, E_);
    mma_gemm<1><<<g1, 256, GEMM_SMEM>>>(fc1_b, nullptr);
    mma_gemm<2><<<g1, 256, GEMM_SMEM>>>(fc2_b, nullptr);
    combine_kernel<<<(B_*(H_/4))/256, 256>>>();
    dim3 gf(O_/128, B_/128);
    mma_gemm<0><<<gf, 256, GEMM_SMEM>>>(final_b, out);
}